// round 6
// baseline (speedup 1.0000x reference)
#include <cuda_runtime.h>
#include <cuda_bf16.h>

#define NODE_DIM 64
#define EDGE_DIM 32
#define HIDDEN   128
#define MAXN     100000
#define MAXE     800000
#define LN_EPS   1e-5f

typedef unsigned long long u64;

// ---------------- scratch (no allocs allowed) ----------------
__device__ __align__(16) float g_xs[MAXN * HIDDEN];   // x @ W_src
__device__ __align__(16) float g_xd[MAXN * HIDDEN];   // x @ W_dst
__device__ __align__(16) float g_S [MAXN * HIDDEN];   // per-dst sum of edge activations
__device__ __align__(16) float g_c [HIDDEN];          // b_msg2 @ W_upd1[64:192]

// CSR grouping of edges by dst
__device__ int g_hist[MAXN];
__device__ int g_cur [MAXN];
__device__ int g_off [MAXN + 1];
__device__ int g_srcS[MAXE];
__device__ int g_eS  [MAXE];

// pair-interleaved weights: W_p[k/2][col][2] with W_p[kp][c][h] = W[2kp+h][c]
__device__ __align__(16) float g_Wsrc_p[32 * 128 * 2]; // W_msg1 rows   0..63
__device__ __align__(16) float g_Wdst_p[32 * 128 * 2]; // W_msg1 rows  64..127
__device__ __align__(16) float g_We_p [16 * 128 * 2];  // W_msg1 rows 128..159
__device__ __align__(16) float g_Wa_p [32 * 128 * 2];  // W_upd1 rows   0..63
__device__ __align__(16) float g_Wf_p [64 * 128 * 2];  // W_msg2 @ W_upd1[64:192]
__device__ __align__(16) float g_W2_p [64 * 64  * 2];  // W_upd2 (128x64)

// ---------------- helpers ----------------
__device__ __forceinline__ u64 pk(float lo, float hi) {
    u64 r; asm("mov.b64 %0,{%1,%2};" : "=l"(r) : "f"(lo), "f"(hi)); return r;
}
__device__ __forceinline__ void fma2(u64& d, u64 a, u64 b) {
    asm("fma.rn.f32x2 %0,%1,%2,%0;" : "+l"(d) : "l"(a), "l"(b));
}
__device__ __forceinline__ float psum(u64 v) {
    float lo, hi; asm("mov.b64 {%0,%1},%2;" : "=f"(lo), "=f"(hi) : "l"(v));
    return lo + hi;
}
__device__ __forceinline__ float warp_sum(float v) {
#pragma unroll
    for (int o = 16; o > 0; o >>= 1) v += __shfl_xor_sync(0xffffffffu, v, o);
    return v;
}
__device__ __forceinline__ float silu_f(float y) {
    return y * (1.0f / (1.0f + __expf(-y)));
}

// ---------------- K0a: fold W_msg2 through W_upd1 (agg part) ----------------
__global__ void k_fuse(const float* __restrict__ Wmsg2,
                       const float* __restrict__ Wupd1,
                       const float* __restrict__ bmsg2) {
    int k = blockIdx.x;      // 0..127
    int t = threadIdx.x;     // 0..127
    float acc = 0.f;
#pragma unroll 8
    for (int j = 0; j < HIDDEN; ++j)
        acc = fmaf(Wmsg2[k * HIDDEN + j], Wupd1[(NODE_DIM + j) * HIDDEN + t], acc);
    g_Wf_p[(k >> 1) * 256 + t * 2 + (k & 1)] = acc;
    if (k == 0) {
        float c = 0.f;
#pragma unroll 8
        for (int j = 0; j < HIDDEN; ++j)
            c = fmaf(bmsg2[j], Wupd1[(NODE_DIM + j) * HIDDEN + t], c);
        g_c[t] = c;
    }
}

// ---------------- K0b: build pair-interleaved weight copies ----------------
__global__ void k_prep(const float* __restrict__ Wmsg1,
                       const float* __restrict__ Wupd1,
                       const float* __restrict__ Wupd2) {
    int idx = blockIdx.x * blockDim.x + threadIdx.x;
    if (idx < 8192) {                       // Wsrc: rows 0..63 of Wmsg1
        int k = idx >> 7, c = idx & 127;
        g_Wsrc_p[(k >> 1) * 256 + c * 2 + (k & 1)] = Wmsg1[k * 128 + c];
    } else if (idx < 16384) {               // Wdst: rows 64..127
        int r = idx - 8192; int k = r >> 7, c = r & 127;
        g_Wdst_p[(k >> 1) * 256 + c * 2 + (k & 1)] = Wmsg1[(64 + k) * 128 + c];
    } else if (idx < 20480) {               // We: rows 128..159
        int r = idx - 16384; int k = r >> 7, c = r & 127;
        g_We_p[(k >> 1) * 256 + c * 2 + (k & 1)] = Wmsg1[(128 + k) * 128 + c];
    } else if (idx < 28672) {               // Wa: rows 0..63 of Wupd1
        int r = idx - 20480; int k = r >> 7, c = r & 127;
        g_Wa_p[(k >> 1) * 256 + c * 2 + (k & 1)] = Wupd1[k * 128 + c];
    } else if (idx < 36864) {               // W2: Wupd2 (128x64)
        int r = idx - 28672; int k = r >> 6, c = r & 63;
        g_W2_p[(k >> 1) * 128 + c * 2 + (k & 1)] = Wupd2[k * 64 + c];
    }
}

// ---------------- CSR build: histogram / scan / scatter ----------------
__global__ void k_hist(const int* __restrict__ ei, int E) {
    for (int i = blockIdx.x * blockDim.x + threadIdx.x; i < E;
         i += gridDim.x * blockDim.x)
        atomicAdd(&g_hist[ei[E + i]], 1);
}

__global__ void k_scan(int N) {
    __shared__ int ssum[1024];
    const int t = threadIdx.x;
    const int chunk = (N + 1023) >> 10;
    const int lo = t * chunk;
    const int hi = min(lo + chunk, N);
    int s = 0;
#pragma unroll 4
    for (int i = lo; i < hi; ++i) s += g_hist[i];
    ssum[t] = s;
    __syncthreads();
#pragma unroll
    for (int o = 1; o < 1024; o <<= 1) {
        int v = 0;
        if (t >= o) v = ssum[t - o];
        __syncthreads();
        if (t >= o) ssum[t] += v;
        __syncthreads();
    }
    int run = (t == 0) ? 0 : ssum[t - 1];
    for (int i = lo; i < hi; ++i) {
        g_off[i] = run;
        g_cur[i] = run;
        run += g_hist[i];
    }
    if (t == 1023) g_off[N] = run;
}

__global__ void k_scatter(const int* __restrict__ ei, int E) {
    for (int e = blockIdx.x * blockDim.x + threadIdx.x; e < E;
         e += gridDim.x * blockDim.x) {
        const int d = ei[E + e];
        const int pos = atomicAdd(&g_cur[d], 1);
        g_srcS[pos] = ei[e];
        g_eS[pos] = e;
    }
}

// ---------------- K1: xs = x@W_src, xd = x@W_dst (warp per 4 nodes, FFMA2) ----------
__global__ __launch_bounds__(256)
void k_node_proj(const float* __restrict__ x, int N) {
    extern __shared__ float sm[];
    float* sWs = sm;             // 32*128*2 = 8192
    float* sWd = sWs + 8192;     // 8192
    float* sX  = sWd + 8192;     // 8 warps * 4 nodes * 64 = 2048
    {
        float4* d0 = (float4*)sWs; const float4* s0 = (const float4*)g_Wsrc_p;
        float4* d1 = (float4*)sWd; const float4* s1 = (const float4*)g_Wdst_p;
        for (int i = threadIdx.x; i < 2048; i += blockDim.x) { d0[i] = s0[i]; d1[i] = s1[i]; }
    }
    __syncthreads();
    const int lane = threadIdx.x & 31, warp = threadIdx.x >> 5;
    const int gw = blockIdx.x * 8 + warp;
    const int nwarps = gridDim.x * 8;
    float* myX = &sX[warp * 4 * 64];

    for (int base = gw * 4; base < N; base += nwarps * 4) {
        __syncwarp();
#pragma unroll
        for (int j = 0; j < 4; ++j) {
            const int n = base + j;
            float2 xv = make_float2(0.f, 0.f);
            if (n < N) xv = *(const float2*)&x[n * NODE_DIM + lane * 2];
            *(float2*)&myX[j * 64 + lane * 2] = xv;
        }
        __syncwarp();
        u64 aS[4][4], aD[4][4];
#pragma unroll
        for (int j = 0; j < 4; ++j)
#pragma unroll
            for (int cc = 0; cc < 4; ++cc) { aS[j][cc] = 0ull; aD[j][cc] = 0ull; }
#pragma unroll
        for (int kp = 0; kp < 32; ++kp) {
            const ulonglong2 ws01 = *(const ulonglong2*)&sWs[kp * 256 + lane * 8];
            const ulonglong2 ws23 = *(const ulonglong2*)&sWs[kp * 256 + lane * 8 + 4];
            const ulonglong2 wd01 = *(const ulonglong2*)&sWd[kp * 256 + lane * 8];
            const ulonglong2 wd23 = *(const ulonglong2*)&sWd[kp * 256 + lane * 8 + 4];
#pragma unroll
            for (int j = 0; j < 4; ++j) {
                const u64 a = *(const u64*)&myX[j * 64 + kp * 2];
                fma2(aS[j][0], a, ws01.x); fma2(aS[j][1], a, ws01.y);
                fma2(aS[j][2], a, ws23.x); fma2(aS[j][3], a, ws23.y);
                fma2(aD[j][0], a, wd01.x); fma2(aD[j][1], a, wd01.y);
                fma2(aD[j][2], a, wd23.x); fma2(aD[j][3], a, wd23.y);
            }
        }
#pragma unroll
        for (int j = 0; j < 4; ++j) {
            const int n = base + j;
            if (n < N) {
                float4 os = make_float4(psum(aS[j][0]), psum(aS[j][1]),
                                        psum(aS[j][2]), psum(aS[j][3]));
                float4 od = make_float4(psum(aD[j][0]), psum(aD[j][1]),
                                        psum(aD[j][2]), psum(aD[j][3]));
                *(float4*)&g_xs[(size_t)n * HIDDEN + lane * 4] = os;
                *(float4*)&g_xd[(size_t)n * HIDDEN + lane * 4] = od;
            }
        }
    }
}

// ---------------- K2: grouped edge kernel (warp per dst node) ----------------
__global__ __launch_bounds__(256)
void k_edge_g(const float* __restrict__ ea, const float* __restrict__ b1,
              const float* __restrict__ gm, const float* __restrict__ bem, int N) {
    __shared__ __align__(16) float sWe[16 * 256];   // pair-interleaved edge weights
    __shared__ __align__(16) float sb[HIDDEN];
    __shared__ __align__(16) float sg[HIDDEN];
    __shared__ __align__(16) float sbe[HIDDEN];
    __shared__ __align__(16) float sE[8 * 4 * 32];  // staged edge attrs per warp
    for (int i = threadIdx.x; i < 16 * 256; i += blockDim.x) sWe[i] = g_We_p[i];
    for (int i = threadIdx.x; i < HIDDEN; i += blockDim.x) {
        sb[i] = b1[i]; sg[i] = gm[i]; sbe[i] = bem[i];
    }
    __syncthreads();
    const int lane = threadIdx.x & 31, warp = threadIdx.x >> 5;
    const int gw = blockIdx.x * 8 + warp;
    const int nwarps = gridDim.x * 8;
    float* myE = &sE[warp * 128];
    const float4 bb  = *(const float4*)&sb[lane * 4];
    const float4 gv  = *(const float4*)&sg[lane * 4];
    const float4 bev = *(const float4*)&sbe[lane * 4];

    for (int n = gw; n < N; n += nwarps) {
        const int s = g_off[n];
        const int eEnd = g_off[n + 1];
        float4 accS = make_float4(0.f, 0.f, 0.f, 0.f);
        if (s < eEnd) {
            const float4 xd4 = *(const float4*)&g_xd[(size_t)n * HIDDEN + lane * 4];
            float4 base;
            base.x = xd4.x + bb.x; base.y = xd4.y + bb.y;
            base.z = xd4.z + bb.z; base.w = xd4.w + bb.w;
            for (int gb = s; gb < eEnd; gb += 4) {
                const int m = min(4, eEnd - gb);
                __syncwarp();
#pragma unroll
                for (int j = 0; j < 4; ++j) {
                    if (j < m) {
                        const int eo = g_eS[gb + j];
                        myE[j * 32 + lane] = ea[(size_t)eo * EDGE_DIM + lane];
                    }
                }
                __syncwarp();
                u64 acc[4][4];
#pragma unroll
                for (int j = 0; j < 4; ++j) {
                    const int idx = gb + ((j < m) ? j : 0);
                    const int src = g_srcS[idx];
                    const float4 xs4 = *(const float4*)&g_xs[(size_t)src * HIDDEN + lane * 4];
                    acc[j][0] = pk(base.x + xs4.x, 0.f);
                    acc[j][1] = pk(base.y + xs4.y, 0.f);
                    acc[j][2] = pk(base.z + xs4.z, 0.f);
                    acc[j][3] = pk(base.w + xs4.w, 0.f);
                }
#pragma unroll
                for (int kp = 0; kp < 16; ++kp) {
                    const ulonglong2 w01 = *(const ulonglong2*)&sWe[kp * 256 + lane * 8];
                    const ulonglong2 w23 = *(const ulonglong2*)&sWe[kp * 256 + lane * 8 + 4];
#pragma unroll
                    for (int j = 0; j < 4; ++j) {
                        const u64 a = *(const u64*)&myE[j * 32 + kp * 2];
                        fma2(acc[j][0], a, w01.x); fma2(acc[j][1], a, w01.y);
                        fma2(acc[j][2], a, w23.x); fma2(acc[j][3], a, w23.y);
                    }
                }
#pragma unroll
                for (int j = 0; j < 4; ++j) {
                    if (j < m) {
                        const float v0 = psum(acc[j][0]), v1 = psum(acc[j][1]);
                        const float v2 = psum(acc[j][2]), v3 = psum(acc[j][3]);
                        float sT = warp_sum(v0 + v1 + v2 + v3);
                        const float mu = sT * (1.0f / HIDDEN);
                        const float dx = v0 - mu, dy = v1 - mu, dz = v2 - mu, dw = v3 - mu;
                        float ss = warp_sum(dx * dx + dy * dy + dz * dz + dw * dw);
                        const float rstd = rsqrtf(ss * (1.0f / HIDDEN) + LN_EPS);
                        accS.x += silu_f(dx * rstd * gv.x + bev.x);
                        accS.y += silu_f(dy * rstd * gv.y + bev.y);
                        accS.z += silu_f(dz * rstd * gv.z + bev.z);
                        accS.w += silu_f(dw * rstd * gv.w + bev.w);
                    }
                }
            }
        }
        *(float4*)&g_S[(size_t)n * HIDDEN + lane * 4] = accS;
    }
}

// ---------------- K3: fused node update (warp per 4 nodes, FFMA2) ----------------
__global__ __launch_bounds__(256, 1)
void k_update(const float* __restrict__ x,
              const float* __restrict__ bupd1,
              const float* __restrict__ gu, const float* __restrict__ beu,
              const float* __restrict__ bupd2,
              float* __restrict__ out, int N) {
    extern __shared__ float sm[];
    float* sWa = sm;                       // 32*128*2 = 8192
    float* sWf = sWa + 8192;               // 64*128*2 = 16384
    float* sW2 = sWf + 16384;              // 64*64*2  = 8192
    float* sb1 = sW2 + 8192;               // 128
    float* sc  = sb1 + HIDDEN;             // 128
    float* sg  = sc  + HIDDEN;             // 128
    float* sbe = sg  + HIDDEN;             // 128
    float* sb2 = sbe + HIDDEN;             // 64
    float* sT  = sb2 + NODE_DIM;           // 8 warps * 4 nodes * 192 = 6144
    {
        float4* d = (float4*)sWa; const float4* s = (const float4*)g_Wa_p;
        for (int i = threadIdx.x; i < 2048; i += blockDim.x) d[i] = s[i];
        d = (float4*)sWf; s = (const float4*)g_Wf_p;
        for (int i = threadIdx.x; i < 4096; i += blockDim.x) d[i] = s[i];
        d = (float4*)sW2; s = (const float4*)g_W2_p;
        for (int i = threadIdx.x; i < 2048; i += blockDim.x) d[i] = s[i];
    }
    for (int i = threadIdx.x; i < HIDDEN; i += blockDim.x) {
        sb1[i] = bupd1[i]; sc[i] = g_c[i]; sg[i] = gu[i]; sbe[i] = beu[i];
    }
    for (int i = threadIdx.x; i < NODE_DIM; i += blockDim.x) sb2[i] = bupd2[i];
    __syncthreads();

    const int lane = threadIdx.x & 31, warp = threadIdx.x >> 5;
    const int gw = blockIdx.x * 8 + warp;
    const int nwarps = gridDim.x * 8;
    float* myT = &sT[warp * 4 * 192];   // per node: [0..63]=x, [64..191]=S then act

    const float4 b1v = *(const float4*)&sb1[lane * 4];
    const float4 cv  = *(const float4*)&sc [lane * 4];
    const float4 gv  = *(const float4*)&sg [lane * 4];
    const float4 bev = *(const float4*)&sbe[lane * 4];
    const float2 b2v = *(const float2*)&sb2[lane * 2];

    for (int base = gw * 4; base < N; base += nwarps * 4) {
        __syncwarp();
        u64 acc[4][4];
#pragma unroll
        for (int j = 0; j < 4; ++j) {
            const int n = base + j;
            float2 xv = make_float2(0.f, 0.f);
            float4 s4 = make_float4(0.f, 0.f, 0.f, 0.f);
            float dg = 0.f;
            if (n < N) {
                xv = *(const float2*)&x[n * NODE_DIM + lane * 2];
                s4 = *(const float4*)&g_S[(size_t)n * HIDDEN + lane * 4];
                dg = (float)g_hist[n];
            }
            *(float2*)&myT[j * 192 + lane * 2] = xv;
            *(float4*)&myT[j * 192 + 64 + lane * 4] = s4;
            acc[j][0] = pk(fmaf(dg, cv.x, b1v.x), 0.f);
            acc[j][1] = pk(fmaf(dg, cv.y, b1v.y), 0.f);
            acc[j][2] = pk(fmaf(dg, cv.z, b1v.z), 0.f);
            acc[j][3] = pk(fmaf(dg, cv.w, b1v.w), 0.f);
        }
        __syncwarp();
        // loop1: x @ W_upd1[0:64]   (k = 64 -> 32 pair-steps)
#pragma unroll
        for (int kp = 0; kp < 32; ++kp) {
            const ulonglong2 w01 = *(const ulonglong2*)&sWa[kp * 256 + lane * 8];
            const ulonglong2 w23 = *(const ulonglong2*)&sWa[kp * 256 + lane * 8 + 4];
#pragma unroll
            for (int j = 0; j < 4; ++j) {
                const u64 a = *(const u64*)&myT[j * 192 + kp * 2];
                fma2(acc[j][0], a, w01.x); fma2(acc[j][1], a, w01.y);
                fma2(acc[j][2], a, w23.x); fma2(acc[j][3], a, w23.y);
            }
        }
        // loop2: S @ Wf   (k = 128 -> 64 pair-steps)
#pragma unroll
        for (int kp = 0; kp < 64; ++kp) {
            const ulonglong2 w01 = *(const ulonglong2*)&sWf[kp * 256 + lane * 8];
            const ulonglong2 w23 = *(const ulonglong2*)&sWf[kp * 256 + lane * 8 + 4];
#pragma unroll
            for (int j = 0; j < 4; ++j) {
                const u64 a = *(const u64*)&myT[j * 192 + 64 + kp * 2];
                fma2(acc[j][0], a, w01.x); fma2(acc[j][1], a, w01.y);
                fma2(acc[j][2], a, w23.x); fma2(acc[j][3], a, w23.y);
            }
        }
        __syncwarp();
        // LayerNorm + SiLU, store act into the S slots
#pragma unroll
        for (int j = 0; j < 4; ++j) {
            const float v0 = psum(acc[j][0]), v1 = psum(acc[j][1]);
            const float v2 = psum(acc[j][2]), v3 = psum(acc[j][3]);
            float s = warp_sum(v0 + v1 + v2 + v3);
            const float mu = s * (1.0f / HIDDEN);
            const float dx = v0 - mu, dy = v1 - mu, dz = v2 - mu, dw = v3 - mu;
            float ss = warp_sum(dx * dx + dy * dy + dz * dz + dw * dw);
            const float rstd = rsqrtf(ss * (1.0f / HIDDEN) + LN_EPS);
            float4 act;
            act.x = silu_f(dx * rstd * gv.x + bev.x);
            act.y = silu_f(dy * rstd * gv.y + bev.y);
            act.z = silu_f(dz * rstd * gv.z + bev.z);
            act.w = silu_f(dw * rstd * gv.w + bev.w);
            *(float4*)&myT[j * 192 + 64 + lane * 4] = act;
        }
        __syncwarp();
        // loop3: act @ W_upd2 (128 -> 64), lane owns cols lane*2, lane*2+1
        u64 o0[4], o1[4];
#pragma unroll
        for (int j = 0; j < 4; ++j) { o0[j] = 0ull; o1[j] = 0ull; }
#pragma unroll
        for (int kp = 0; kp < 64; ++kp) {
            const ulonglong2 w = *(const ulonglong2*)&sW2[kp * 128 + lane * 4];
#pragma unroll
            for (int j = 0; j < 4; ++j) {
                const u64 a = *(const u64*)&myT[j * 192 + 64 + kp * 2];
                fma2(o0[j], a, w.x); fma2(o1[j], a, w.y);
            }
        }
#pragma unroll
        for (int j = 0; j < 4; ++j) {
            const int n = base + j;
            if (n < N) {
                const float2 xv = *(const float2*)&myT[j * 192 + lane * 2];
                float2 res;
                res.x = xv.x + psum(o0[j]) + b2v.x;
                res.y = xv.y + psum(o1[j]) + b2v.y;
                *(float2*)&out[(size_t)n * NODE_DIM + lane * 2] = res;
            }
        }
    }
}

// ---------------- host ----------------
extern "C" void kernel_launch(void* const* d_in, const int* in_sizes, int n_in,
                              void* d_out, int out_size) {
    const float* x      = (const float*)d_in[0];
    const int*   ei     = (const int*)  d_in[1];
    const float* ea     = (const float*)d_in[2];
    const float* Wmsg1  = (const float*)d_in[3];
    const float* bmsg1  = (const float*)d_in[4];
    const float* gmsg   = (const float*)d_in[5];
    const float* bemsg  = (const float*)d_in[6];
    const float* Wmsg2  = (const float*)d_in[7];
    const float* bmsg2  = (const float*)d_in[8];
    const float* Wupd1  = (const float*)d_in[9];
    const float* bupd1  = (const float*)d_in[10];
    const float* gupd   = (const float*)d_in[11];
    const float* beupd  = (const float*)d_in[12];
    const float* Wupd2  = (const float*)d_in[13];
    const float* bupd2  = (const float*)d_in[14];
    float* out = (float*)d_out;

    const int N = in_sizes[0] / NODE_DIM;
    const int E = in_sizes[2] / EDGE_DIM;

    void* pHist = nullptr;
    cudaGetSymbolAddress(&pHist, g_hist);
    cudaMemsetAsync(pHist, 0, (size_t)N * sizeof(int), 0);

    const int smem_proj = (8192 + 8192 + 2048) * sizeof(float);                    // 72 KB
    const int smem_upd  = (8192 + 16384 + 8192 + 4 * HIDDEN + NODE_DIM + 6144) * sizeof(float); // ~158 KB
    cudaFuncSetAttribute(k_node_proj, cudaFuncAttributeMaxDynamicSharedMemorySize, smem_proj);
    cudaFuncSetAttribute(k_update,    cudaFuncAttributeMaxDynamicSharedMemorySize, smem_upd);

    k_fuse<<<HIDDEN, HIDDEN>>>(Wmsg2, Wupd1, bmsg2);
    k_prep<<<144, 256>>>(Wmsg1, Wupd1, Wupd2);
    k_hist<<<592, 256>>>(ei, E);
    k_scan<<<1, 1024>>>(N);
    k_scatter<<<592, 256>>>(ei, E);
    k_node_proj<<<296, 256, smem_proj>>>(x, N);
    k_edge_g<<<1184, 256>>>(ea, bmsg1, gmsg, bemsg, N);
    k_update<<<148, 256, smem_upd>>>(x, bupd1, gupd, beupd, bupd2, out, N);
}

// round 7
// speedup vs baseline: 1.2521x; 1.2521x over previous
#include <cuda_runtime.h>
#include <cuda_bf16.h>

#define NODE_DIM 64
#define EDGE_DIM 32
#define HIDDEN   128
#define MAXN     100000
#define MAXE     800000
#define LN_EPS   1e-5f

typedef unsigned long long u64;

// ---------------- scratch (no allocs allowed) ----------------
__device__ __align__(16) float g_xs[MAXN * HIDDEN];   // x @ W_src
__device__ __align__(16) float g_xd[MAXN * HIDDEN];   // x @ W_dst + b_msg1
__device__ __align__(16) float g_S [MAXN * HIDDEN];   // per-dst sum of edge activations
__device__ __align__(16) float g_c [HIDDEN];          // b_msg2 @ W_upd1[64:192]
__device__ __align__(16) float g_Wf_p[64 * 128 * 2];  // pair-interleaved W_msg2 @ W_upd1[64:192]

// CSR grouping of edges by dst
__device__ int g_hist[MAXN];
__device__ int g_cur [MAXN];
__device__ int g_off [MAXN + 1];
__device__ int g_part[256];
__device__ int g_srcS[MAXE];
__device__ int g_eS  [MAXE];

// ---------------- helpers ----------------
__device__ __forceinline__ u64 pk(float lo, float hi) {
    u64 r; asm("mov.b64 %0,{%1,%2};" : "=l"(r) : "f"(lo), "f"(hi)); return r;
}
__device__ __forceinline__ void fma2(u64& d, u64 a, u64 b) {
    asm("fma.rn.f32x2 %0,%1,%2,%0;" : "+l"(d) : "l"(a), "l"(b));
}
__device__ __forceinline__ float psum(u64 v) {
    float lo, hi; asm("mov.b64 {%0,%1},%2;" : "=f"(lo), "=f"(hi) : "l"(v));
    return lo + hi;
}
__device__ __forceinline__ float silu_f(float y) {
    return y * (1.0f / (1.0f + __expf(-y)));
}

// ---------------- CSR build ----------------
__global__ void k_hist(const int* __restrict__ ei, int E) {
    for (int i = blockIdx.x * blockDim.x + threadIdx.x; i < E;
         i += gridDim.x * blockDim.x)
        atomicAdd(&g_hist[ei[E + i]], 1);
}

// scanA: per-block sums of 512 hist entries
__global__ __launch_bounds__(512)
void k_scanA(int N) {
    __shared__ int sm[512];
    const int t = threadIdx.x;
    const int i = blockIdx.x * 512 + t;
    sm[t] = (i < N) ? g_hist[i] : 0;
    __syncthreads();
#pragma unroll
    for (int o = 256; o > 0; o >>= 1) {
        if (t < o) sm[t] += sm[t + o];
        __syncthreads();
    }
    if (t == 0) g_part[blockIdx.x] = sm[0];
}

// scanB: every block scans the partials redundantly, then block-scans its chunk
__global__ __launch_bounds__(512)
void k_scanB(int N, int nblk) {
    __shared__ int sp[256];
    __shared__ int sm[512];
    const int t = threadIdx.x;
    if (t < 256) sp[t] = (t < nblk) ? g_part[t] : 0;
    __syncthreads();
#pragma unroll
    for (int o = 1; o < 256; o <<= 1) {
        int u = 0;
        if (t < 256 && t >= o) u = sp[t - o];
        __syncthreads();
        if (t < 256) sp[t] += u;
        __syncthreads();
    }
    const int base = (blockIdx.x == 0) ? 0 : sp[blockIdx.x - 1];
    const int total = sp[nblk - 1];
    const int i = blockIdx.x * 512 + t;
    const int v = (i < N) ? g_hist[i] : 0;
    sm[t] = v;
    __syncthreads();
#pragma unroll
    for (int o = 1; o < 512; o <<= 1) {
        int u = 0;
        if (t >= o) u = sm[t - o];
        __syncthreads();
        sm[t] += u;
        __syncthreads();
    }
    const int excl = base + sm[t] - v;
    if (i < N) { g_off[i] = excl; g_cur[i] = excl; }
    if (blockIdx.x == 0 && t == 0) g_off[N] = total;
}

__global__ void k_scatter(const int* __restrict__ ei, int E) {
    for (int e = blockIdx.x * blockDim.x + threadIdx.x; e < E;
         e += gridDim.x * blockDim.x) {
        const int d = ei[E + e];
        const int pos = atomicAdd(&g_cur[d], 1);
        g_srcS[pos] = ei[e];
        g_eS[pos] = e;
    }
}

// ---------------- K fuse: Wf = W_msg2 @ W_upd1[64:192] (pair-interleaved), c ----------
__global__ void k_fuse(const float* __restrict__ Wmsg2,
                       const float* __restrict__ Wupd1,
                       const float* __restrict__ bmsg2) {
    int k = blockIdx.x;      // 0..127
    int t = threadIdx.x;     // 0..127
    float acc = 0.f;
#pragma unroll 8
    for (int j = 0; j < HIDDEN; ++j)
        acc = fmaf(Wmsg2[k * HIDDEN + j], Wupd1[(NODE_DIM + j) * HIDDEN + t], acc);
    g_Wf_p[(k >> 1) * 256 + t * 2 + (k & 1)] = acc;
    if (k == 0) {
        float c = 0.f;
#pragma unroll 8
        for (int j = 0; j < HIDDEN; ++j)
            c = fmaf(bmsg2[j], Wupd1[(NODE_DIM + j) * HIDDEN + t], c);
        g_c[t] = c;
    }
}

// ---------------- K node_proj: xs = x@W_src, xd = x@W_dst + b1 ----------------
__global__ __launch_bounds__(256)
void k_node_proj(const float* __restrict__ x,
                 const float* __restrict__ Wmsg1,
                 const float* __restrict__ b1, int N) {
    extern __shared__ float sm[];
    float* sWs = sm;             // 32*128*2 = 8192 (pair-interleaved)
    float* sWd = sWs + 8192;     // 8192
    float* sX  = sWd + 8192;     // 8 warps * 4 nodes * 64 = 2048
    for (int i = threadIdx.x; i < 8192; i += blockDim.x) {
        const int k = i >> 7, c = i & 127;
        const int idx = (k >> 1) * 256 + c * 2 + (k & 1);
        sWs[idx] = Wmsg1[i];
        sWd[idx] = Wmsg1[8192 + i];
    }
    __syncthreads();
    const int lane = threadIdx.x & 31, warp = threadIdx.x >> 5;
    const int gw = blockIdx.x * 8 + warp;
    const int nwarps = gridDim.x * 8;
    float* myX = &sX[warp * 4 * 64];
    const float4 b1v = *(const float4*)&b1[lane * 4];

    for (int base = gw * 4; base < N; base += nwarps * 4) {
        __syncwarp();
#pragma unroll
        for (int j = 0; j < 4; ++j) {
            const int n = base + j;
            float2 xv = make_float2(0.f, 0.f);
            if (n < N) xv = *(const float2*)&x[n * NODE_DIM + lane * 2];
            *(float2*)&myX[j * 64 + lane * 2] = xv;
        }
        __syncwarp();
        u64 aS[4][4], aD[4][4];
#pragma unroll
        for (int j = 0; j < 4; ++j)
#pragma unroll
            for (int cc = 0; cc < 4; ++cc) { aS[j][cc] = 0ull; aD[j][cc] = 0ull; }
#pragma unroll
        for (int kp = 0; kp < 32; ++kp) {
            const ulonglong2 ws01 = *(const ulonglong2*)&sWs[kp * 256 + lane * 8];
            const ulonglong2 ws23 = *(const ulonglong2*)&sWs[kp * 256 + lane * 8 + 4];
            const ulonglong2 wd01 = *(const ulonglong2*)&sWd[kp * 256 + lane * 8];
            const ulonglong2 wd23 = *(const ulonglong2*)&sWd[kp * 256 + lane * 8 + 4];
#pragma unroll
            for (int j = 0; j < 4; ++j) {
                const u64 a = *(const u64*)&myX[j * 64 + kp * 2];
                fma2(aS[j][0], a, ws01.x); fma2(aS[j][1], a, ws01.y);
                fma2(aS[j][2], a, ws23.x); fma2(aS[j][3], a, ws23.y);
                fma2(aD[j][0], a, wd01.x); fma2(aD[j][1], a, wd01.y);
                fma2(aD[j][2], a, wd23.x); fma2(aD[j][3], a, wd23.y);
            }
        }
#pragma unroll
        for (int j = 0; j < 4; ++j) {
            const int n = base + j;
            if (n < N) {
                float4 os = make_float4(psum(aS[j][0]), psum(aS[j][1]),
                                        psum(aS[j][2]), psum(aS[j][3]));
                float4 od = make_float4(psum(aD[j][0]) + b1v.x, psum(aD[j][1]) + b1v.y,
                                        psum(aD[j][2]) + b1v.z, psum(aD[j][3]) + b1v.w);
                *(float4*)&g_xs[(size_t)n * HIDDEN + lane * 4] = os;
                *(float4*)&g_xd[(size_t)n * HIDDEN + lane * 4] = od;
            }
        }
    }
}

// ---------------- edge batch (templated size) ----------------
template<int B>
__device__ __forceinline__ float4 edge_batch(
    int gb, int lane, float* myE, const float* __restrict__ ea,
    const float4 base, const float* sWe, const float4 gv, const float4 bev)
{
    __syncwarp();
#pragma unroll
    for (int j = 0; j < B; ++j) {
        const int eo = g_eS[gb + j];
        myE[j * 32 + lane] = ea[(size_t)eo * EDGE_DIM + lane];
    }
    __syncwarp();
    u64 acc[B][4];
#pragma unroll
    for (int j = 0; j < B; ++j) {
        const int src = g_srcS[gb + j];
        const float4 xs4 = *(const float4*)&g_xs[(size_t)src * HIDDEN + lane * 4];
        acc[j][0] = pk(base.x + xs4.x, 0.f);
        acc[j][1] = pk(base.y + xs4.y, 0.f);
        acc[j][2] = pk(base.z + xs4.z, 0.f);
        acc[j][3] = pk(base.w + xs4.w, 0.f);
    }
#pragma unroll
    for (int kp = 0; kp < 16; ++kp) {
        const ulonglong2 w01 = *(const ulonglong2*)&sWe[kp * 256 + lane * 8];
        const ulonglong2 w23 = *(const ulonglong2*)&sWe[kp * 256 + lane * 8 + 4];
#pragma unroll
        for (int j = 0; j < B; ++j) {
            const u64 a = *(const u64*)&myE[j * 32 + kp * 2];
            fma2(acc[j][0], a, w01.x); fma2(acc[j][1], a, w01.y);
            fma2(acc[j][2], a, w23.x); fma2(acc[j][3], a, w23.y);
        }
    }
    float4 out = make_float4(0.f, 0.f, 0.f, 0.f);
#pragma unroll
    for (int j = 0; j < B; ++j) {
        const float v0 = psum(acc[j][0]), v1 = psum(acc[j][1]);
        const float v2 = psum(acc[j][2]), v3 = psum(acc[j][3]);
        float s1 = v0 + v1 + v2 + v3;
        float s2 = fmaf(v0, v0, fmaf(v1, v1, fmaf(v2, v2, v3 * v3)));
#pragma unroll
        for (int o = 16; o > 0; o >>= 1) {
            s1 += __shfl_xor_sync(0xffffffffu, s1, o);
            s2 += __shfl_xor_sync(0xffffffffu, s2, o);
        }
        const float mu = s1 * (1.0f / HIDDEN);
        const float var = fmaf(-mu, mu, s2 * (1.0f / HIDDEN));
        const float rstd = rsqrtf(var + LN_EPS);
        out.x += silu_f((v0 - mu) * rstd * gv.x + bev.x);
        out.y += silu_f((v1 - mu) * rstd * gv.y + bev.y);
        out.z += silu_f((v2 - mu) * rstd * gv.z + bev.z);
        out.w += silu_f((v3 - mu) * rstd * gv.w + bev.w);
    }
    return out;
}

// ---------------- K edge: grouped edge kernel (warp per dst node) ----------------
__global__ __launch_bounds__(256)
void k_edge_g(const float* __restrict__ ea, const float* __restrict__ Wmsg1,
              const float* __restrict__ gm, const float* __restrict__ bem, int N) {
    __shared__ __align__(16) float sWe[16 * 256];   // pair-interleaved edge weights
    __shared__ __align__(16) float sg[HIDDEN];
    __shared__ __align__(16) float sbe[HIDDEN];
    __shared__ __align__(16) float sE[8 * 4 * 32];  // staged edge attrs per warp
    for (int i = threadIdx.x; i < 4096; i += blockDim.x) {
        const int k = i >> 7, c = i & 127;
        sWe[(k >> 1) * 256 + c * 2 + (k & 1)] = Wmsg1[16384 + i];
    }
    for (int i = threadIdx.x; i < HIDDEN; i += blockDim.x) {
        sg[i] = gm[i]; sbe[i] = bem[i];
    }
    __syncthreads();
    const int lane = threadIdx.x & 31, warp = threadIdx.x >> 5;
    const int gw = blockIdx.x * 8 + warp;
    const int nwarps = gridDim.x * 8;
    float* myE = &sE[warp * 128];
    const float4 gv  = *(const float4*)&sg[lane * 4];
    const float4 bev = *(const float4*)&sbe[lane * 4];

    for (int n = gw; n < N; n += nwarps) {
        const int s = g_off[n];
        const int eEnd = g_off[n + 1];
        float4 accS = make_float4(0.f, 0.f, 0.f, 0.f);
        if (s < eEnd) {
            const float4 base = *(const float4*)&g_xd[(size_t)n * HIDDEN + lane * 4];
            int gb = s;
            for (; gb + 4 <= eEnd; gb += 4) {
                const float4 r = edge_batch<4>(gb, lane, myE, ea, base, sWe, gv, bev);
                accS.x += r.x; accS.y += r.y; accS.z += r.z; accS.w += r.w;
            }
            const int rem = eEnd - gb;
            float4 r = make_float4(0.f, 0.f, 0.f, 0.f);
            if (rem == 3)      r = edge_batch<3>(gb, lane, myE, ea, base, sWe, gv, bev);
            else if (rem == 2) r = edge_batch<2>(gb, lane, myE, ea, base, sWe, gv, bev);
            else if (rem == 1) r = edge_batch<1>(gb, lane, myE, ea, base, sWe, gv, bev);
            accS.x += r.x; accS.y += r.y; accS.z += r.z; accS.w += r.w;
        }
        *(float4*)&g_S[(size_t)n * HIDDEN + lane * 4] = accS;
    }
}

// ---------------- K update: fused node update (warp per 4 nodes, FFMA2) ----------------
__global__ __launch_bounds__(256, 1)
void k_update(const float* __restrict__ x,
              const float* __restrict__ Wupd1, const float* __restrict__ bupd1,
              const float* __restrict__ gu, const float* __restrict__ beu,
              const float* __restrict__ Wupd2, const float* __restrict__ bupd2,
              float* __restrict__ out, int N) {
    extern __shared__ float sm[];
    float* sWa = sm;                       // 32*128*2 = 8192
    float* sWf = sWa + 8192;               // 64*128*2 = 16384
    float* sW2 = sWf + 16384;              // 64*64*2  = 8192
    float* sb1 = sW2 + 8192;               // 128
    float* sc  = sb1 + HIDDEN;             // 128
    float* sg  = sc  + HIDDEN;             // 128
    float* sbe = sg  + HIDDEN;             // 128
    float* sb2 = sbe + HIDDEN;             // 64
    float* sT  = sb2 + NODE_DIM;           // 8 warps * 4 nodes * 192 = 6144
    for (int i = threadIdx.x; i < 8192; i += blockDim.x) {
        const int k = i >> 7, c = i & 127;
        sWa[(k >> 1) * 256 + c * 2 + (k & 1)] = Wupd1[i];
        const int k2 = i >> 6, c2 = i & 63;
        sW2[(k2 >> 1) * 128 + c2 * 2 + (k2 & 1)] = Wupd2[i];
    }
    {
        float4* d = (float4*)sWf; const float4* s = (const float4*)g_Wf_p;
        for (int i = threadIdx.x; i < 4096; i += blockDim.x) d[i] = s[i];
    }
    for (int i = threadIdx.x; i < HIDDEN; i += blockDim.x) {
        sb1[i] = bupd1[i]; sc[i] = g_c[i]; sg[i] = gu[i]; sbe[i] = beu[i];
    }
    for (int i = threadIdx.x; i < NODE_DIM; i += blockDim.x) sb2[i] = bupd2[i];
    __syncthreads();

    const int lane = threadIdx.x & 31, warp = threadIdx.x >> 5;
    const int gw = blockIdx.x * 8 + warp;
    const int nwarps = gridDim.x * 8;
    float* myT = &sT[warp * 4 * 192];   // per node: [0..63]=x, [64..191]=S then act

    const float4 b1v = *(const float4*)&sb1[lane * 4];
    const float4 cv  = *(const float4*)&sc [lane * 4];
    const float4 gv  = *(const float4*)&sg [lane * 4];
    const float4 bev = *(const float4*)&sbe[lane * 4];
    const float2 b2v = *(const float2*)&sb2[lane * 2];

    for (int base = gw * 4; base < N; base += nwarps * 4) {
        __syncwarp();
        u64 acc[4][4];
#pragma unroll
        for (int j = 0; j < 4; ++j) {
            const int n = base + j;
            float2 xv = make_float2(0.f, 0.f);
            float4 s4 = make_float4(0.f, 0.f, 0.f, 0.f);
            float dg = 0.f;
            if (n < N) {
                xv = *(const float2*)&x[n * NODE_DIM + lane * 2];
                s4 = *(const float4*)&g_S[(size_t)n * HIDDEN + lane * 4];
                dg = (float)g_hist[n];
            }
            *(float2*)&myT[j * 192 + lane * 2] = xv;
            *(float4*)&myT[j * 192 + 64 + lane * 4] = s4;
            acc[j][0] = pk(fmaf(dg, cv.x, b1v.x), 0.f);
            acc[j][1] = pk(fmaf(dg, cv.y, b1v.y), 0.f);
            acc[j][2] = pk(fmaf(dg, cv.z, b1v.z), 0.f);
            acc[j][3] = pk(fmaf(dg, cv.w, b1v.w), 0.f);
        }
        __syncwarp();
        // loop1: x @ W_upd1[0:64]
#pragma unroll
        for (int kp = 0; kp < 32; ++kp) {
            const ulonglong2 w01 = *(const ulonglong2*)&sWa[kp * 256 + lane * 8];
            const ulonglong2 w23 = *(const ulonglong2*)&sWa[kp * 256 + lane * 8 + 4];
#pragma unroll
            for (int j = 0; j < 4; ++j) {
                const u64 a = *(const u64*)&myT[j * 192 + kp * 2];
                fma2(acc[j][0], a, w01.x); fma2(acc[j][1], a, w01.y);
                fma2(acc[j][2], a, w23.x); fma2(acc[j][3], a, w23.y);
            }
        }
        // loop2: S @ Wf
#pragma unroll
        for (int kp = 0; kp < 64; ++kp) {
            const ulonglong2 w01 = *(const ulonglong2*)&sWf[kp * 256 + lane * 8];
            const ulonglong2 w23 = *(const ulonglong2*)&sWf[kp * 256 + lane * 8 + 4];
#pragma unroll
            for (int j = 0; j < 4; ++j) {
                const u64 a = *(const u64*)&myT[j * 192 + 64 + kp * 2];
                fma2(acc[j][0], a, w01.x); fma2(acc[j][1], a, w01.y);
                fma2(acc[j][2], a, w23.x); fma2(acc[j][3], a, w23.y);
            }
        }
        __syncwarp();
        // LayerNorm (one pass) + SiLU, store act into the S slots
#pragma unroll
        for (int j = 0; j < 4; ++j) {
            const float v0 = psum(acc[j][0]), v1 = psum(acc[j][1]);
            const float v2 = psum(acc[j][2]), v3 = psum(acc[j][3]);
            float s1 = v0 + v1 + v2 + v3;
            float s2 = fmaf(v0, v0, fmaf(v1, v1, fmaf(v2, v2, v3 * v3)));
#pragma unroll
            for (int o = 16; o > 0; o >>= 1) {
                s1 += __shfl_xor_sync(0xffffffffu, s1, o);
                s2 += __shfl_xor_sync(0xffffffffu, s2, o);
            }
            const float mu = s1 * (1.0f / HIDDEN);
            const float var = fmaf(-mu, mu, s2 * (1.0f / HIDDEN));
            const float rstd = rsqrtf(var + LN_EPS);
            float4 act;
            act.x = silu_f((v0 - mu) * rstd * gv.x + bev.x);
            act.y = silu_f((v1 - mu) * rstd * gv.y + bev.y);
            act.z = silu_f((v2 - mu) * rstd * gv.z + bev.z);
            act.w = silu_f((v3 - mu) * rstd * gv.w + bev.w);
            *(float4*)&myT[j * 192 + 64 + lane * 4] = act;
        }
        __syncwarp();
        // loop3: act @ W_upd2 (128 -> 64)
        u64 o0[4], o1[4];
#pragma unroll
        for (int j = 0; j < 4; ++j) { o0[j] = 0ull; o1[j] = 0ull; }
#pragma unroll
        for (int kp = 0; kp < 64; ++kp) {
            const ulonglong2 w = *(const ulonglong2*)&sW2[kp * 128 + lane * 4];
#pragma unroll
            for (int j = 0; j < 4; ++j) {
                const u64 a = *(const u64*)&myT[j * 192 + 64 + kp * 2];
                fma2(o0[j], a, w.x); fma2(o1[j], a, w.y);
            }
        }
#pragma unroll
        for (int j = 0; j < 4; ++j) {
            const int n = base + j;
            if (n < N) {
                const float2 xv = *(const float2*)&myT[j * 192 + lane * 2];
                float2 res;
                res.x = xv.x + psum(o0[j]) + b2v.x;
                res.y = xv.y + psum(o1[j]) + b2v.y;
                *(float2*)&out[(size_t)n * NODE_DIM + lane * 2] = res;
            }
        }
    }
}

// ---------------- host ----------------
extern "C" void kernel_launch(void* const* d_in, const int* in_sizes, int n_in,
                              void* d_out, int out_size) {
    const float* x      = (const float*)d_in[0];
    const int*   ei     = (const int*)  d_in[1];
    const float* ea     = (const float*)d_in[2];
    const float* Wmsg1  = (const float*)d_in[3];
    const float* bmsg1  = (const float*)d_in[4];
    const float* gmsg   = (const float*)d_in[5];
    const float* bemsg  = (const float*)d_in[6];
    const float* Wmsg2  = (const float*)d_in[7];
    const float* bmsg2  = (const float*)d_in[8];
    const float* Wupd1  = (const float*)d_in[9];
    const float* bupd1  = (const float*)d_in[10];
    const float* gupd   = (const float*)d_in[11];
    const float* beupd  = (const float*)d_in[12];
    const float* Wupd2  = (const float*)d_in[13];
    const float* bupd2  = (const float*)d_in[14];
    float* out = (float*)d_out;

    const int N = in_sizes[0] / NODE_DIM;
    const int E = in_sizes[2] / EDGE_DIM;
    const int nblk = (N + 511) / 512;

    void* pHist = nullptr;
    cudaGetSymbolAddress(&pHist, g_hist);
    cudaMemsetAsync(pHist, 0, (size_t)N * sizeof(int), 0);

    const int smem_proj = (8192 + 8192 + 2048) * sizeof(float);                    // 72 KB
    const int smem_upd  = (8192 + 16384 + 8192 + 4 * HIDDEN + NODE_DIM + 6144) * sizeof(float); // ~158 KB
    cudaFuncSetAttribute(k_node_proj, cudaFuncAttributeMaxDynamicSharedMemorySize, smem_proj);
    cudaFuncSetAttribute(k_update,    cudaFuncAttributeMaxDynamicSharedMemorySize, smem_upd);

    // order chosen so the profiler's captured launch (4th kernel) = k_scatter
    k_hist<<<592, 256>>>(ei, E);
    k_scanA<<<nblk, 512>>>(N);
    k_scanB<<<nblk, 512>>>(N, nblk);
    k_scatter<<<592, 256>>>(ei, E);
    k_node_proj<<<296, 256, smem_proj>>>(x, Wmsg1, bmsg1, N);
    k_fuse<<<HIDDEN, HIDDEN>>>(Wmsg2, Wupd1, bmsg2);
    k_edge_g<<<1184, 256>>>(ea, Wmsg1, gmsg, bemsg, N);
    k_update<<<148, 256, smem_upd>>>(x, Wupd1, bupd1, gupd, beupd, Wupd2, bupd2, out, N);
}

// round 8
// speedup vs baseline: 1.5271x; 1.2196x over previous
#include <cuda_runtime.h>
#include <cuda_bf16.h>

#define NODE_DIM 64
#define EDGE_DIM 32
#define HIDDEN   128
#define MAXN     100000
#define MAXE     800000
#define LN_EPS   1e-5f

typedef unsigned long long u64;

// ---------------- scratch (no allocs allowed) ----------------
__device__ __align__(16) float g_xs[MAXN * HIDDEN];   // x @ W_src
__device__ __align__(16) float g_xd[MAXN * HIDDEN];   // x @ W_dst + b_msg1
__device__ __align__(16) float g_S [MAXN * HIDDEN];   // scatter-sum of edge activations
__device__ __align__(16) float g_deg[MAXN];           // in-degree (float)
__device__ __align__(16) float g_c [HIDDEN];          // b_msg2 @ W_upd1[64:192]
__device__ __align__(16) float g_Wf_p[64 * 128 * 2];  // pair-interleaved W_msg2 @ W_upd1[64:192]

// ---------------- helpers ----------------
__device__ __forceinline__ u64 pk(float lo, float hi) {
    u64 r; asm("mov.b64 %0,{%1,%2};" : "=l"(r) : "f"(lo), "f"(hi)); return r;
}
__device__ __forceinline__ void fma2(u64& d, u64 a, u64 b) {
    asm("fma.rn.f32x2 %0,%1,%2,%0;" : "+l"(d) : "l"(a), "l"(b));
}
__device__ __forceinline__ float psum(u64 v) {
    float lo, hi; asm("mov.b64 {%0,%1},%2;" : "=f"(lo), "=f"(hi) : "l"(v));
    return lo + hi;
}
__device__ __forceinline__ float silu_f(float y) {
    return y * (1.0f / (1.0f + __expf(-y)));
}
__device__ __forceinline__ void red_add_v4(float* p, float4 v) {
    asm volatile("red.global.add.v4.f32 [%0], {%1,%2,%3,%4};"
                 :: "l"(p), "f"(v.x), "f"(v.y), "f"(v.z), "f"(v.w) : "memory");
}

// ---------------- K fuse: Wf = W_msg2 @ W_upd1[64:192] (pair-interleaved), c ----------
__global__ void k_fuse(const float* __restrict__ Wmsg2,
                       const float* __restrict__ Wupd1,
                       const float* __restrict__ bmsg2) {
    int k = blockIdx.x;      // 0..127
    int t = threadIdx.x;     // 0..127
    float acc = 0.f;
#pragma unroll 8
    for (int j = 0; j < HIDDEN; ++j)
        acc = fmaf(Wmsg2[k * HIDDEN + j], Wupd1[(NODE_DIM + j) * HIDDEN + t], acc);
    g_Wf_p[(k >> 1) * 256 + t * 2 + (k & 1)] = acc;
    if (k == 0) {
        float c = 0.f;
#pragma unroll 8
        for (int j = 0; j < HIDDEN; ++j)
            c = fmaf(bmsg2[j], Wupd1[(NODE_DIM + j) * HIDDEN + t], c);
        g_c[t] = c;
    }
}

// ---------------- no-op spacer (aligns ncu's 4th-launch capture onto k_edge) ------
__global__ void k_nop() {}

// ---------------- K node_proj: xs = x@W_src, xd = x@W_dst + b1 (FFMA2) ----------
__global__ __launch_bounds__(256)
void k_node_proj(const float* __restrict__ x,
                 const float* __restrict__ Wmsg1,
                 const float* __restrict__ b1, int N) {
    extern __shared__ float sm[];
    float* sWs = sm;             // 32*128*2 = 8192 (pair-interleaved)
    float* sWd = sWs + 8192;     // 8192
    float* sX  = sWd + 8192;     // 8 warps * 4 nodes * 64 = 2048
    for (int i = threadIdx.x; i < 8192; i += blockDim.x) {
        const int k = i >> 7, c = i & 127;
        const int idx = (k >> 1) * 256 + c * 2 + (k & 1);
        sWs[idx] = Wmsg1[i];
        sWd[idx] = Wmsg1[8192 + i];
    }
    __syncthreads();
    const int lane = threadIdx.x & 31, warp = threadIdx.x >> 5;
    const int gw = blockIdx.x * 8 + warp;
    const int nwarps = gridDim.x * 8;
    float* myX = &sX[warp * 4 * 64];
    const float4 b1v = *(const float4*)&b1[lane * 4];

    for (int base = gw * 4; base < N; base += nwarps * 4) {
        __syncwarp();
#pragma unroll
        for (int j = 0; j < 4; ++j) {
            const int n = base + j;
            float2 xv = make_float2(0.f, 0.f);
            if (n < N) xv = *(const float2*)&x[n * NODE_DIM + lane * 2];
            *(float2*)&myX[j * 64 + lane * 2] = xv;
        }
        __syncwarp();
        u64 aS[4][4], aD[4][4];
#pragma unroll
        for (int j = 0; j < 4; ++j)
#pragma unroll
            for (int cc = 0; cc < 4; ++cc) { aS[j][cc] = 0ull; aD[j][cc] = 0ull; }
#pragma unroll
        for (int kp = 0; kp < 32; ++kp) {
            const ulonglong2 ws01 = *(const ulonglong2*)&sWs[kp * 256 + lane * 8];
            const ulonglong2 ws23 = *(const ulonglong2*)&sWs[kp * 256 + lane * 8 + 4];
            const ulonglong2 wd01 = *(const ulonglong2*)&sWd[kp * 256 + lane * 8];
            const ulonglong2 wd23 = *(const ulonglong2*)&sWd[kp * 256 + lane * 8 + 4];
#pragma unroll
            for (int j = 0; j < 4; ++j) {
                const u64 a = *(const u64*)&myX[j * 64 + kp * 2];
                fma2(aS[j][0], a, ws01.x); fma2(aS[j][1], a, ws01.y);
                fma2(aS[j][2], a, ws23.x); fma2(aS[j][3], a, ws23.y);
                fma2(aD[j][0], a, wd01.x); fma2(aD[j][1], a, wd01.y);
                fma2(aD[j][2], a, wd23.x); fma2(aD[j][3], a, wd23.y);
            }
        }
#pragma unroll
        for (int j = 0; j < 4; ++j) {
            const int n = base + j;
            if (n < N) {
                float4 os = make_float4(psum(aS[j][0]), psum(aS[j][1]),
                                        psum(aS[j][2]), psum(aS[j][3]));
                float4 od = make_float4(psum(aD[j][0]) + b1v.x, psum(aD[j][1]) + b1v.y,
                                        psum(aD[j][2]) + b1v.z, psum(aD[j][3]) + b1v.w);
                *(float4*)&g_xs[(size_t)n * HIDDEN + lane * 4] = os;
                *(float4*)&g_xd[(size_t)n * HIDDEN + lane * 4] = od;
            }
        }
    }
}

// ---------------- K edge: warp per 4 edges, shuffle broadcast, atomic scatter ------
__global__ __launch_bounds__(256)
void k_edge(const int* __restrict__ ei, const float* __restrict__ ea,
            const float* __restrict__ Wmsg1,
            const float* __restrict__ gm, const float* __restrict__ bem, int E) {
    __shared__ __align__(16) float sWe[EDGE_DIM * HIDDEN]; // rows 128..159 of W_msg1
    __shared__ __align__(16) float sg[HIDDEN];
    __shared__ __align__(16) float sbe[HIDDEN];
    for (int i = threadIdx.x; i < EDGE_DIM * HIDDEN; i += blockDim.x)
        sWe[i] = Wmsg1[HIDDEN * HIDDEN + i];
    for (int i = threadIdx.x; i < HIDDEN; i += blockDim.x) {
        sg[i] = gm[i]; sbe[i] = bem[i];
    }
    __syncthreads();
    const int lane = threadIdx.x & 31, warp = threadIdx.x >> 5;
    const int gw = blockIdx.x * 8 + warp;
    const int nwarps = gridDim.x * 8;
    const float4 gv  = *(const float4*)&sg[lane * 4];
    const float4 bev = *(const float4*)&sbe[lane * 4];

    for (int base = gw * 4; base < E; base += nwarps * 4) {
        int dsts[4];
        float eav[4];
        float4 acc[4];
#pragma unroll
        for (int j = 0; j < 4; ++j) {
            const int e = base + j;
            if (e < E) {
                const int src = ei[e];
                dsts[j] = ei[E + e];
                const float4 vs = *(const float4*)&g_xs[(size_t)src * HIDDEN + lane * 4];
                const float4 vd = *(const float4*)&g_xd[(size_t)dsts[j] * HIDDEN + lane * 4];
                acc[j].x = vs.x + vd.x;
                acc[j].y = vs.y + vd.y;
                acc[j].z = vs.z + vd.z;
                acc[j].w = vs.w + vd.w;
                eav[j] = ea[(size_t)e * EDGE_DIM + lane];
            } else {
                dsts[j] = -1;
                acc[j] = make_float4(0.f, 0.f, 0.f, 0.f);
                eav[j] = 0.f;
            }
        }
#pragma unroll
        for (int k = 0; k < 32; ++k) {
            const float4 w = *(const float4*)&sWe[k * HIDDEN + lane * 4];
#pragma unroll
            for (int j = 0; j < 4; ++j) {
                const float a = __shfl_sync(0xffffffffu, eav[j], k);
                acc[j].x = fmaf(a, w.x, acc[j].x);
                acc[j].y = fmaf(a, w.y, acc[j].y);
                acc[j].z = fmaf(a, w.z, acc[j].z);
                acc[j].w = fmaf(a, w.w, acc[j].w);
            }
        }
#pragma unroll
        for (int j = 0; j < 4; ++j) {
            if (dsts[j] < 0) continue;
            float s1 = acc[j].x + acc[j].y + acc[j].z + acc[j].w;
            float s2 = fmaf(acc[j].x, acc[j].x, fmaf(acc[j].y, acc[j].y,
                       fmaf(acc[j].z, acc[j].z, acc[j].w * acc[j].w)));
#pragma unroll
            for (int o = 16; o > 0; o >>= 1) {
                s1 += __shfl_xor_sync(0xffffffffu, s1, o);
                s2 += __shfl_xor_sync(0xffffffffu, s2, o);
            }
            const float mu = s1 * (1.0f / HIDDEN);
            const float var = fmaf(-mu, mu, s2 * (1.0f / HIDDEN));
            const float rstd = rsqrtf(var + LN_EPS);
            float4 act;
            act.x = silu_f((acc[j].x - mu) * rstd * gv.x + bev.x);
            act.y = silu_f((acc[j].y - mu) * rstd * gv.y + bev.y);
            act.z = silu_f((acc[j].z - mu) * rstd * gv.z + bev.z);
            act.w = silu_f((acc[j].w - mu) * rstd * gv.w + bev.w);
            red_add_v4(&g_S[(size_t)dsts[j] * HIDDEN + lane * 4], act);
            if (lane == 0) atomicAdd(&g_deg[dsts[j]], 1.0f);
        }
    }
}

// ---------------- K update: fused node update (warp per 4 nodes, FFMA2) ----------------
__global__ __launch_bounds__(256, 1)
void k_update(const float* __restrict__ x,
              const float* __restrict__ Wupd1, const float* __restrict__ bupd1,
              const float* __restrict__ gu, const float* __restrict__ beu,
              const float* __restrict__ Wupd2, const float* __restrict__ bupd2,
              float* __restrict__ out, int N) {
    extern __shared__ float sm[];
    float* sWa = sm;                       // 32*128*2 = 8192
    float* sWf = sWa + 8192;               // 64*128*2 = 16384
    float* sW2 = sWf + 16384;              // 64*64*2  = 8192
    float* sb1 = sW2 + 8192;               // 128
    float* sc  = sb1 + HIDDEN;             // 128
    float* sg  = sc  + HIDDEN;             // 128
    float* sbe = sg  + HIDDEN;             // 128
    float* sb2 = sbe + HIDDEN;             // 64
    float* sT  = sb2 + NODE_DIM;           // 8 warps * 4 nodes * 192 = 6144
    for (int i = threadIdx.x; i < 8192; i += blockDim.x) {
        const int k = i >> 7, c = i & 127;
        sWa[(k >> 1) * 256 + c * 2 + (k & 1)] = Wupd1[i];
        const int k2 = i >> 6, c2 = i & 63;
        sW2[(k2 >> 1) * 128 + c2 * 2 + (k2 & 1)] = Wupd2[i];
    }
    {
        float4* d = (float4*)sWf; const float4* s = (const float4*)g_Wf_p;
        for (int i = threadIdx.x; i < 4096; i += blockDim.x) d[i] = s[i];
    }
    for (int i = threadIdx.x; i < HIDDEN; i += blockDim.x) {
        sb1[i] = bupd1[i]; sc[i] = g_c[i]; sg[i] = gu[i]; sbe[i] = beu[i];
    }
    for (int i = threadIdx.x; i < NODE_DIM; i += blockDim.x) sb2[i] = bupd2[i];
    __syncthreads();

    const int lane = threadIdx.x & 31, warp = threadIdx.x >> 5;
    const int gw = blockIdx.x * 8 + warp;
    const int nwarps = gridDim.x * 8;
    float* myT = &sT[warp * 4 * 192];   // per node: [0..63]=x, [64..191]=S then act

    const float4 b1v = *(const float4*)&sb1[lane * 4];
    const float4 cv  = *(const float4*)&sc [lane * 4];
    const float4 gv  = *(const float4*)&sg [lane * 4];
    const float4 bev = *(const float4*)&sbe[lane * 4];
    const float2 b2v = *(const float2*)&sb2[lane * 2];

    for (int base = gw * 4; base < N; base += nwarps * 4) {
        __syncwarp();
        u64 acc[4][4];
#pragma unroll
        for (int j = 0; j < 4; ++j) {
            const int n = base + j;
            float2 xv = make_float2(0.f, 0.f);
            float4 s4 = make_float4(0.f, 0.f, 0.f, 0.f);
            float dg = 0.f;
            if (n < N) {
                xv = *(const float2*)&x[n * NODE_DIM + lane * 2];
                s4 = *(const float4*)&g_S[(size_t)n * HIDDEN + lane * 4];
                dg = g_deg[n];
            }
            *(float2*)&myT[j * 192 + lane * 2] = xv;
            *(float4*)&myT[j * 192 + 64 + lane * 4] = s4;
            acc[j][0] = pk(fmaf(dg, cv.x, b1v.x), 0.f);
            acc[j][1] = pk(fmaf(dg, cv.y, b1v.y), 0.f);
            acc[j][2] = pk(fmaf(dg, cv.z, b1v.z), 0.f);
            acc[j][3] = pk(fmaf(dg, cv.w, b1v.w), 0.f);
        }
        __syncwarp();
        // loop1: x @ W_upd1[0:64]
#pragma unroll
        for (int kp = 0; kp < 32; ++kp) {
            const ulonglong2 w01 = *(const ulonglong2*)&sWa[kp * 256 + lane * 8];
            const ulonglong2 w23 = *(const ulonglong2*)&sWa[kp * 256 + lane * 8 + 4];
#pragma unroll
            for (int j = 0; j < 4; ++j) {
                const u64 a = *(const u64*)&myT[j * 192 + kp * 2];
                fma2(acc[j][0], a, w01.x); fma2(acc[j][1], a, w01.y);
                fma2(acc[j][2], a, w23.x); fma2(acc[j][3], a, w23.y);
            }
        }
        // loop2: S @ Wf
#pragma unroll
        for (int kp = 0; kp < 64; ++kp) {
            const ulonglong2 w01 = *(const ulonglong2*)&sWf[kp * 256 + lane * 8];
            const ulonglong2 w23 = *(const ulonglong2*)&sWf[kp * 256 + lane * 8 + 4];
#pragma unroll
            for (int j = 0; j < 4; ++j) {
                const u64 a = *(const u64*)&myT[j * 192 + 64 + kp * 2];
                fma2(acc[j][0], a, w01.x); fma2(acc[j][1], a, w01.y);
                fma2(acc[j][2], a, w23.x); fma2(acc[j][3], a, w23.y);
            }
        }
        __syncwarp();
        // LayerNorm (one pass) + SiLU, store act into the S slots
#pragma unroll
        for (int j = 0; j < 4; ++j) {
            const float v0 = psum(acc[j][0]), v1 = psum(acc[j][1]);
            const float v2 = psum(acc[j][2]), v3 = psum(acc[j][3]);
            float s1 = v0 + v1 + v2 + v3;
            float s2 = fmaf(v0, v0, fmaf(v1, v1, fmaf(v2, v2, v3 * v3)));
#pragma unroll
            for (int o = 16; o > 0; o >>= 1) {
                s1 += __shfl_xor_sync(0xffffffffu, s1, o);
                s2 += __shfl_xor_sync(0xffffffffu, s2, o);
            }
            const float mu = s1 * (1.0f / HIDDEN);
            const float var = fmaf(-mu, mu, s2 * (1.0f / HIDDEN));
            const float rstd = rsqrtf(var + LN_EPS);
            float4 act;
            act.x = silu_f((v0 - mu) * rstd * gv.x + bev.x);
            act.y = silu_f((v1 - mu) * rstd * gv.y + bev.y);
            act.z = silu_f((v2 - mu) * rstd * gv.z + bev.z);
            act.w = silu_f((v3 - mu) * rstd * gv.w + bev.w);
            *(float4*)&myT[j * 192 + 64 + lane * 4] = act;
        }
        __syncwarp();
        // loop3: act @ W_upd2 (128 -> 64)
        u64 o0[4], o1[4];
#pragma unroll
        for (int j = 0; j < 4; ++j) { o0[j] = 0ull; o1[j] = 0ull; }
#pragma unroll
        for (int kp = 0; kp < 64; ++kp) {
            const ulonglong2 w = *(const ulonglong2*)&sW2[kp * 128 + lane * 4];
#pragma unroll
            for (int j = 0; j < 4; ++j) {
                const u64 a = *(const u64*)&myT[j * 192 + 64 + kp * 2];
                fma2(o0[j], a, w.x); fma2(o1[j], a, w.y);
            }
        }
#pragma unroll
        for (int j = 0; j < 4; ++j) {
            const int n = base + j;
            if (n < N) {
                const float2 xv = *(const float2*)&myT[j * 192 + lane * 2];
                float2 res;
                res.x = xv.x + psum(o0[j]) + b2v.x;
                res.y = xv.y + psum(o1[j]) + b2v.y;
                *(float2*)&out[(size_t)n * NODE_DIM + lane * 2] = res;
            }
        }
    }
}

// ---------------- host ----------------
extern "C" void kernel_launch(void* const* d_in, const int* in_sizes, int n_in,
                              void* d_out, int out_size) {
    const float* x      = (const float*)d_in[0];
    const int*   ei     = (const int*)  d_in[1];
    const float* ea     = (const float*)d_in[2];
    const float* Wmsg1  = (const float*)d_in[3];
    const float* bmsg1  = (const float*)d_in[4];
    const float* gmsg   = (const float*)d_in[5];
    const float* bemsg  = (const float*)d_in[6];
    const float* Wmsg2  = (const float*)d_in[7];
    const float* bmsg2  = (const float*)d_in[8];
    const float* Wupd1  = (const float*)d_in[9];
    const float* bupd1  = (const float*)d_in[10];
    const float* gupd   = (const float*)d_in[11];
    const float* beupd  = (const float*)d_in[12];
    const float* Wupd2  = (const float*)d_in[13];
    const float* bupd2  = (const float*)d_in[14];
    float* out = (float*)d_out;

    const int N = in_sizes[0] / NODE_DIM;
    const int E = in_sizes[2] / EDGE_DIM;

    void *pS = nullptr, *pdeg = nullptr;
    cudaGetSymbolAddress(&pS, g_S);
    cudaGetSymbolAddress(&pdeg, g_deg);
    cudaMemsetAsync(pS, 0, (size_t)N * HIDDEN * sizeof(float), 0);
    cudaMemsetAsync(pdeg, 0, (size_t)N * sizeof(float), 0);

    const int smem_proj = (8192 + 8192 + 2048) * sizeof(float);                    // 72 KB
    const int smem_upd  = (8192 + 16384 + 8192 + 4 * HIDDEN + NODE_DIM + 6144) * sizeof(float); // ~158 KB
    cudaFuncSetAttribute(k_node_proj, cudaFuncAttributeMaxDynamicSharedMemorySize, smem_proj);
    cudaFuncSetAttribute(k_update,    cudaFuncAttributeMaxDynamicSharedMemorySize, smem_upd);

    // launch order: 4th non-memset kernel = k_edge (ncu capture target)
    k_fuse<<<HIDDEN, HIDDEN>>>(Wmsg2, Wupd1, bmsg2);
    k_node_proj<<<296, 256, smem_proj>>>(x, Wmsg1, bmsg1, N);
    k_nop<<<1, 32>>>();
    k_edge<<<1184, 256>>>(ei, ea, Wmsg1, gmsg, bemsg, E);
    k_update<<<148, 256, smem_upd>>>(x, bupd1 ? Wupd1 : Wupd1, bupd1, gupd, beupd, Wupd2, bupd2, out, N);
}

// round 9
// speedup vs baseline: 1.5516x; 1.0160x over previous
#include <cuda_runtime.h>
#include <cuda_bf16.h>

#define NODE_DIM 64
#define EDGE_DIM 32
#define HIDDEN   128
#define MAXN     100000
#define MAXE     800000
#define LN_EPS   1e-5f

typedef unsigned long long u64;

// ---------------- scratch (no allocs allowed) ----------------
__device__ __align__(16) float g_xs[MAXN * HIDDEN];   // x @ W_src
__device__ __align__(16) float g_xd[MAXN * HIDDEN];   // x @ W_dst + b_msg1
__device__ __align__(16) float g_S [MAXN * HIDDEN];   // scatter-sum of edge activations
__device__ __align__(16) float g_deg[MAXN];           // in-degree (float)
__device__ __align__(16) float g_c [HIDDEN];          // b_msg2 @ W_upd1[64:192]
__device__ __align__(16) float g_Wf_p[64 * 128 * 2];  // [kp][cc][lane][h] W_msg2@W_upd1[64:192]

// ---------------- helpers ----------------
__device__ __forceinline__ u64 pk(float lo, float hi) {
    u64 r; asm("mov.b64 %0,{%1,%2};" : "=l"(r) : "f"(lo), "f"(hi)); return r;
}
__device__ __forceinline__ void fma2(u64& d, u64 a, u64 b) {
    asm("fma.rn.f32x2 %0,%1,%2,%0;" : "+l"(d) : "l"(a), "l"(b));
}
__device__ __forceinline__ float psum(u64 v) {
    float lo, hi; asm("mov.b64 {%0,%1},%2;" : "=f"(lo), "=f"(hi) : "l"(v));
    return lo + hi;
}
__device__ __forceinline__ float silu_f(float y) {
    return y * (1.0f / (1.0f + __expf(-y)));
}
__device__ __forceinline__ void red_add_v4(float* p, float4 v) {
    asm volatile("red.global.add.v4.f32 [%0], {%1,%2,%3,%4};"
                 :: "l"(p), "f"(v.x), "f"(v.y), "f"(v.z), "f"(v.w) : "memory");
}

// conflict-free pair layout index: W[k][c] -> base[((kp*4+cc)*32 + lane)*2 + h]
// kp=k>>1, h=k&1, lane=c>>2, cc=c&3 ; LDS.64 per (kp,cc) has 8B lane stride.
__device__ __forceinline__ int pidx(int k, int c) {
    return (((k >> 1) * 4 + (c & 3)) * 32 + (c >> 2)) * 2 + (k & 1);
}

// ---------------- K fuse: Wf = W_msg2 @ W_upd1[64:192] ----------
__global__ void k_fuse(const float* __restrict__ Wmsg2,
                       const float* __restrict__ Wupd1,
                       const float* __restrict__ bmsg2) {
    int k = blockIdx.x;      // 0..127
    int t = threadIdx.x;     // 0..127
    float acc = 0.f;
#pragma unroll 8
    for (int j = 0; j < HIDDEN; ++j)
        acc = fmaf(Wmsg2[k * HIDDEN + j], Wupd1[(NODE_DIM + j) * HIDDEN + t], acc);
    g_Wf_p[pidx(k, t)] = acc;
    if (k == 0) {
        float c = 0.f;
#pragma unroll 8
        for (int j = 0; j < HIDDEN; ++j)
            c = fmaf(bmsg2[j], Wupd1[(NODE_DIM + j) * HIDDEN + t], c);
        g_c[t] = c;
    }
}

// ---------------- no-op spacer (aligns ncu's 4th-launch capture onto k_edge) ------
__global__ void k_nop() {}

// ---------------- K node_proj: xs = x@W_src, xd = x@W_dst + b1 (FFMA2) ----------
__global__ __launch_bounds__(256)
void k_node_proj(const float* __restrict__ x,
                 const float* __restrict__ Wmsg1,
                 const float* __restrict__ b1, int N) {
    extern __shared__ float sm[];
    float* sWs = sm;             // 8192 (pair layout)
    float* sWd = sWs + 8192;     // 8192
    float* sX  = sWd + 8192;     // 8 warps * 4 nodes * 64 = 2048
    for (int i = threadIdx.x; i < 8192; i += blockDim.x) {
        const int k = i >> 7, c = i & 127;
        const int idx = pidx(k, c);
        sWs[idx] = Wmsg1[i];
        sWd[idx] = Wmsg1[8192 + i];
    }
    __syncthreads();
    const int lane = threadIdx.x & 31, warp = threadIdx.x >> 5;
    const int gw = blockIdx.x * 8 + warp;
    const int nwarps = gridDim.x * 8;
    float* myX = &sX[warp * 4 * 64];
    const float4 b1v = *(const float4*)&b1[lane * 4];

    for (int base = gw * 4; base < N; base += nwarps * 4) {
        __syncwarp();
#pragma unroll
        for (int j = 0; j < 4; ++j) {
            const int n = base + j;
            float2 xv = make_float2(0.f, 0.f);
            if (n < N) xv = *(const float2*)&x[n * NODE_DIM + lane * 2];
            *(float2*)&myX[j * 64 + lane * 2] = xv;
        }
        __syncwarp();
        u64 aS[4][4], aD[4][4];
#pragma unroll
        for (int j = 0; j < 4; ++j)
#pragma unroll
            for (int cc = 0; cc < 4; ++cc) { aS[j][cc] = 0ull; aD[j][cc] = 0ull; }
#pragma unroll
        for (int kp = 0; kp < 32; ++kp) {
            u64 ws[4], wd[4];
#pragma unroll
            for (int cc = 0; cc < 4; ++cc) {
                ws[cc] = *(const u64*)&sWs[((kp * 4 + cc) * 32 + lane) * 2];
                wd[cc] = *(const u64*)&sWd[((kp * 4 + cc) * 32 + lane) * 2];
            }
#pragma unroll
            for (int j = 0; j < 4; ++j) {
                const u64 a = *(const u64*)&myX[j * 64 + kp * 2];
                fma2(aS[j][0], a, ws[0]); fma2(aS[j][1], a, ws[1]);
                fma2(aS[j][2], a, ws[2]); fma2(aS[j][3], a, ws[3]);
                fma2(aD[j][0], a, wd[0]); fma2(aD[j][1], a, wd[1]);
                fma2(aD[j][2], a, wd[2]); fma2(aD[j][3], a, wd[3]);
            }
        }
#pragma unroll
        for (int j = 0; j < 4; ++j) {
            const int n = base + j;
            if (n < N) {
                float4 os = make_float4(psum(aS[j][0]), psum(aS[j][1]),
                                        psum(aS[j][2]), psum(aS[j][3]));
                float4 od = make_float4(psum(aD[j][0]) + b1v.x, psum(aD[j][1]) + b1v.y,
                                        psum(aD[j][2]) + b1v.z, psum(aD[j][3]) + b1v.w);
                *(float4*)&g_xs[(size_t)n * HIDDEN + lane * 4] = os;
                *(float4*)&g_xd[(size_t)n * HIDDEN + lane * 4] = od;
            }
        }
    }
}

// ---------------- K edge: warp per 4 edges, FFMA2, atomic scatter ------
__global__ __launch_bounds__(256)
void k_edge(const int* __restrict__ ei, const float* __restrict__ ea,
            const float* __restrict__ Wmsg1,
            const float* __restrict__ gm, const float* __restrict__ bem, int E) {
    __shared__ __align__(16) float sWe[16 * 4 * 32 * 2]; // 4096, pair layout
    __shared__ __align__(16) float sg[HIDDEN];
    __shared__ __align__(16) float sbe[HIDDEN];
    __shared__ __align__(16) float sE[8 * 4 * 32];       // staged edge attrs per warp
    for (int i = threadIdx.x; i < EDGE_DIM * HIDDEN; i += blockDim.x) {
        const int k = i >> 7, c = i & 127;
        sWe[pidx(k, c)] = Wmsg1[HIDDEN * HIDDEN + i];
    }
    for (int i = threadIdx.x; i < HIDDEN; i += blockDim.x) {
        sg[i] = gm[i]; sbe[i] = bem[i];
    }
    __syncthreads();
    const int lane = threadIdx.x & 31, warp = threadIdx.x >> 5;
    const int gw = blockIdx.x * 8 + warp;
    const int nwarps = gridDim.x * 8;
    float* myE = &sE[warp * 128];
    const float4 gv  = *(const float4*)&sg[lane * 4];
    const float4 bev = *(const float4*)&sbe[lane * 4];

    for (int base = gw * 4; base < E; base += nwarps * 4) {
        int dsts[4];
        u64 acc[4][4];
        __syncwarp();
#pragma unroll
        for (int j = 0; j < 4; ++j) {
            const int e = base + j;
            if (e < E) {
                const int src = ei[e];
                dsts[j] = ei[E + e];
                const float4 vs = *(const float4*)&g_xs[(size_t)src * HIDDEN + lane * 4];
                const float4 vd = *(const float4*)&g_xd[(size_t)dsts[j] * HIDDEN + lane * 4];
                acc[j][0] = pk(vs.x + vd.x, 0.f);
                acc[j][1] = pk(vs.y + vd.y, 0.f);
                acc[j][2] = pk(vs.z + vd.z, 0.f);
                acc[j][3] = pk(vs.w + vd.w, 0.f);
                myE[j * 32 + lane] = ea[(size_t)e * EDGE_DIM + lane];
            } else {
                dsts[j] = -1;
                acc[j][0] = acc[j][1] = acc[j][2] = acc[j][3] = 0ull;
                myE[j * 32 + lane] = 0.f;
            }
        }
        __syncwarp();
#pragma unroll
        for (int kp = 0; kp < 16; ++kp) {
            u64 w[4];
#pragma unroll
            for (int cc = 0; cc < 4; ++cc)
                w[cc] = *(const u64*)&sWe[((kp * 4 + cc) * 32 + lane) * 2];
#pragma unroll
            for (int j = 0; j < 4; ++j) {
                const u64 a = *(const u64*)&myE[j * 32 + kp * 2];  // broadcast
                fma2(acc[j][0], a, w[0]); fma2(acc[j][1], a, w[1]);
                fma2(acc[j][2], a, w[2]); fma2(acc[j][3], a, w[3]);
            }
        }
#pragma unroll
        for (int j = 0; j < 4; ++j) {
            if (dsts[j] < 0) continue;
            const float v0 = psum(acc[j][0]), v1 = psum(acc[j][1]);
            const float v2 = psum(acc[j][2]), v3 = psum(acc[j][3]);
            float s1 = v0 + v1 + v2 + v3;
            float s2 = fmaf(v0, v0, fmaf(v1, v1, fmaf(v2, v2, v3 * v3)));
#pragma unroll
            for (int o = 16; o > 0; o >>= 1) {
                s1 += __shfl_xor_sync(0xffffffffu, s1, o);
                s2 += __shfl_xor_sync(0xffffffffu, s2, o);
            }
            const float mu = s1 * (1.0f / HIDDEN);
            const float var = fmaf(-mu, mu, s2 * (1.0f / HIDDEN));
            const float rstd = rsqrtf(var + LN_EPS);
            float4 act;
            act.x = silu_f((v0 - mu) * rstd * gv.x + bev.x);
            act.y = silu_f((v1 - mu) * rstd * gv.y + bev.y);
            act.z = silu_f((v2 - mu) * rstd * gv.z + bev.z);
            act.w = silu_f((v3 - mu) * rstd * gv.w + bev.w);
            red_add_v4(&g_S[(size_t)dsts[j] * HIDDEN + lane * 4], act);
            if (lane == 0) atomicAdd(&g_deg[dsts[j]], 1.0f);
        }
    }
}

// ---------------- K update: fused node update (warp per 4 nodes, FFMA2) ----------------
__global__ __launch_bounds__(256, 1)
void k_update(const float* __restrict__ x,
              const float* __restrict__ Wupd1, const float* __restrict__ bupd1,
              const float* __restrict__ gu, const float* __restrict__ beu,
              const float* __restrict__ Wupd2, const float* __restrict__ bupd2,
              float* __restrict__ out, int N) {
    extern __shared__ float sm[];
    float* sWa = sm;                       // 8192  (pair layout)
    float* sWf = sWa + 8192;               // 16384 (pair layout)
    float* sW2 = sWf + 16384;              // 8192  (old interleave, conflict-free)
    float* sb1 = sW2 + 8192;               // 128
    float* sc  = sb1 + HIDDEN;             // 128
    float* sg  = sc  + HIDDEN;             // 128
    float* sbe = sg  + HIDDEN;             // 128
    float* sb2 = sbe + HIDDEN;             // 64
    float* sT  = sb2 + NODE_DIM;           // 8 warps * 4 nodes * 192 = 6144
    for (int i = threadIdx.x; i < 8192; i += blockDim.x) {
        const int k = i >> 7, c = i & 127;
        sWa[pidx(k, c)] = Wupd1[i];
        const int k2 = i >> 6, c2 = i & 63;
        sW2[(k2 >> 1) * 128 + c2 * 2 + (k2 & 1)] = Wupd2[i];
    }
    {
        float4* d = (float4*)sWf; const float4* s = (const float4*)g_Wf_p;
        for (int i = threadIdx.x; i < 4096; i += blockDim.x) d[i] = s[i];
    }
    for (int i = threadIdx.x; i < HIDDEN; i += blockDim.x) {
        sb1[i] = bupd1[i]; sc[i] = g_c[i]; sg[i] = gu[i]; sbe[i] = beu[i];
    }
    for (int i = threadIdx.x; i < NODE_DIM; i += blockDim.x) sb2[i] = bupd2[i];
    __syncthreads();

    const int lane = threadIdx.x & 31, warp = threadIdx.x >> 5;
    const int gw = blockIdx.x * 8 + warp;
    const int nwarps = gridDim.x * 8;
    float* myT = &sT[warp * 4 * 192];   // per node: [0..63]=x, [64..191]=S then act

    const float4 b1v = *(const float4*)&sb1[lane * 4];
    const float4 cv  = *(const float4*)&sc [lane * 4];
    const float4 gv  = *(const float4*)&sg [lane * 4];
    const float4 bev = *(const float4*)&sbe[lane * 4];
    const float2 b2v = *(const float2*)&sb2[lane * 2];

    for (int base = gw * 4; base < N; base += nwarps * 4) {
        __syncwarp();
        u64 acc[4][4];
#pragma unroll
        for (int j = 0; j < 4; ++j) {
            const int n = base + j;
            float2 xv = make_float2(0.f, 0.f);
            float4 s4 = make_float4(0.f, 0.f, 0.f, 0.f);
            float dg = 0.f;
            if (n < N) {
                xv = *(const float2*)&x[n * NODE_DIM + lane * 2];
                s4 = *(const float4*)&g_S[(size_t)n * HIDDEN + lane * 4];
                dg = g_deg[n];
            }
            *(float2*)&myT[j * 192 + lane * 2] = xv;
            *(float4*)&myT[j * 192 + 64 + lane * 4] = s4;
            acc[j][0] = pk(fmaf(dg, cv.x, b1v.x), 0.f);
            acc[j][1] = pk(fmaf(dg, cv.y, b1v.y), 0.f);
            acc[j][2] = pk(fmaf(dg, cv.z, b1v.z), 0.f);
            acc[j][3] = pk(fmaf(dg, cv.w, b1v.w), 0.f);
        }
        __syncwarp();
        // loop1: x @ W_upd1[0:64]
#pragma unroll
        for (int kp = 0; kp < 32; ++kp) {
            u64 w[4];
#pragma unroll
            for (int cc = 0; cc < 4; ++cc)
                w[cc] = *(const u64*)&sWa[((kp * 4 + cc) * 32 + lane) * 2];
#pragma unroll
            for (int j = 0; j < 4; ++j) {
                const u64 a = *(const u64*)&myT[j * 192 + kp * 2];
                fma2(acc[j][0], a, w[0]); fma2(acc[j][1], a, w[1]);
                fma2(acc[j][2], a, w[2]); fma2(acc[j][3], a, w[3]);
            }
        }
        // loop2: S @ Wf
#pragma unroll
        for (int kp = 0; kp < 64; ++kp) {
            u64 w[4];
#pragma unroll
            for (int cc = 0; cc < 4; ++cc)
                w[cc] = *(const u64*)&sWf[((kp * 4 + cc) * 32 + lane) * 2];
#pragma unroll
            for (int j = 0; j < 4; ++j) {
                const u64 a = *(const u64*)&myT[j * 192 + 64 + kp * 2];
                fma2(acc[j][0], a, w[0]); fma2(acc[j][1], a, w[1]);
                fma2(acc[j][2], a, w[2]); fma2(acc[j][3], a, w[3]);
            }
        }
        __syncwarp();
        // LayerNorm (one pass) + SiLU, store act into the S slots
#pragma unroll
        for (int j = 0; j < 4; ++j) {
            const float v0 = psum(acc[j][0]), v1 = psum(acc[j][1]);
            const float v2 = psum(acc[j][2]), v3 = psum(acc[j][3]);
            float s1 = v0 + v1 + v2 + v3;
            float s2 = fmaf(v0, v0, fmaf(v1, v1, fmaf(v2, v2, v3 * v3)));
#pragma unroll
            for (int o = 16; o > 0; o >>= 1) {
                s1 += __shfl_xor_sync(0xffffffffu, s1, o);
                s2 += __shfl_xor_sync(0xffffffffu, s2, o);
            }
            const float mu = s1 * (1.0f / HIDDEN);
            const float var = fmaf(-mu, mu, s2 * (1.0f / HIDDEN));
            const float rstd = rsqrtf(var + LN_EPS);
            float4 act;
            act.x = silu_f((v0 - mu) * rstd * gv.x + bev.x);
            act.y = silu_f((v1 - mu) * rstd * gv.y + bev.y);
            act.z = silu_f((v2 - mu) * rstd * gv.z + bev.z);
            act.w = silu_f((v3 - mu) * rstd * gv.w + bev.w);
            *(float4*)&myT[j * 192 + 64 + lane * 4] = act;
        }
        __syncwarp();
        // loop3: act @ W_upd2 (128 -> 64)
        u64 o0[4], o1[4];
#pragma unroll
        for (int j = 0; j < 4; ++j) { o0[j] = 0ull; o1[j] = 0ull; }
#pragma unroll
        for (int kp = 0; kp < 64; ++kp) {
            const ulonglong2 w = *(const ulonglong2*)&sW2[kp * 128 + lane * 4];
#pragma unroll
            for (int j = 0; j < 4; ++j) {
                const u64 a = *(const u64*)&myT[j * 192 + 64 + kp * 2];
                fma2(o0[j], a, w.x); fma2(o1[j], a, w.y);
            }
        }
#pragma unroll
        for (int j = 0; j < 4; ++j) {
            const int n = base + j;
            if (n < N) {
                const float2 xv = *(const float2*)&myT[j * 192 + lane * 2];
                float2 res;
                res.x = xv.x + psum(o0[j]) + b2v.x;
                res.y = xv.y + psum(o1[j]) + b2v.y;
                *(float2*)&out[(size_t)n * NODE_DIM + lane * 2] = res;
            }
        }
    }
}

// ---------------- host ----------------
extern "C" void kernel_launch(void* const* d_in, const int* in_sizes, int n_in,
                              void* d_out, int out_size) {
    const float* x      = (const float*)d_in[0];
    const int*   ei     = (const int*)  d_in[1];
    const float* ea     = (const float*)d_in[2];
    const float* Wmsg1  = (const float*)d_in[3];
    const float* bmsg1  = (const float*)d_in[4];
    const float* gmsg   = (const float*)d_in[5];
    const float* bemsg  = (const float*)d_in[6];
    const float* Wmsg2  = (const float*)d_in[7];
    const float* bmsg2  = (const float*)d_in[8];
    const float* Wupd1  = (const float*)d_in[9];
    const float* bupd1  = (const float*)d_in[10];
    const float* gupd   = (const float*)d_in[11];
    const float* beupd  = (const float*)d_in[12];
    const float* Wupd2  = (const float*)d_in[13];
    const float* bupd2  = (const float*)d_in[14];
    float* out = (float*)d_out;

    const int N = in_sizes[0] / NODE_DIM;
    const int E = in_sizes[2] / EDGE_DIM;

    void *pS = nullptr, *pdeg = nullptr;
    cudaGetSymbolAddress(&pS, g_S);
    cudaGetSymbolAddress(&pdeg, g_deg);
    cudaMemsetAsync(pS, 0, (size_t)N * HIDDEN * sizeof(float), 0);
    cudaMemsetAsync(pdeg, 0, (size_t)N * sizeof(float), 0);

    const int smem_proj = (8192 + 8192 + 2048) * sizeof(float);                    // 72 KB
    const int smem_upd  = (8192 + 16384 + 8192 + 4 * HIDDEN + NODE_DIM + 6144) * sizeof(float); // ~158 KB
    cudaFuncSetAttribute(k_node_proj, cudaFuncAttributeMaxDynamicSharedMemorySize, smem_proj);
    cudaFuncSetAttribute(k_update,    cudaFuncAttributeMaxDynamicSharedMemorySize, smem_upd);

    // launch order: 4th non-memset kernel = k_edge (ncu capture target)
    k_fuse<<<HIDDEN, HIDDEN>>>(Wmsg2, Wupd1, bmsg2);
    k_node_proj<<<296, 256, smem_proj>>>(x, Wmsg1, bmsg1, N);
    k_nop<<<1, 32>>>();
    k_edge<<<1184, 256>>>(ei, ea, Wmsg1, gmsg, bemsg, E);
    k_update<<<148, 256, smem_upd>>>(x, Wupd1, bupd1, gupd, beupd, Wupd2, bupd2, out, N);
}

// round 11
// speedup vs baseline: 1.6956x; 1.0928x over previous
#include <cuda_runtime.h>
#include <cuda_bf16.h>

#define NODE_DIM 64
#define EDGE_DIM 32
#define HIDDEN   128
#define MAXN     100000
#define MAXE     800000
#define LN_EPS   1e-5f

typedef unsigned long long u64;

// ---------------- scratch (no allocs allowed) ----------------
__device__ __align__(16) float g_xs[MAXN * HIDDEN];   // x @ W_src
__device__ __align__(16) float g_xd[MAXN * HIDDEN];   // x @ W_dst + b_msg1
__device__ __align__(16) float g_S [MAXN * HIDDEN];   // scatter-sum of edge activations
__device__ __align__(16) float g_deg[MAXN];           // in-degree (float)
__device__ __align__(16) float g_c [HIDDEN];          // b_msg2 @ W_upd1[64:192]
__device__ __align__(16) float g_Wf_p[64 * 128 * 2];  // conflict-free pair layout

// ---------------- helpers ----------------
__device__ __forceinline__ u64 pk(float lo, float hi) {
    u64 r; asm("mov.b64 %0,{%1,%2};" : "=l"(r) : "f"(lo), "f"(hi)); return r;
}
__device__ __forceinline__ void fma2(u64& d, u64 a, u64 b) {
    asm("fma.rn.f32x2 %0,%1,%2,%0;" : "+l"(d) : "l"(a), "l"(b));
}
__device__ __forceinline__ float psum(u64 v) {
    float lo, hi; asm("mov.b64 {%0,%1},%2;" : "=f"(lo), "=f"(hi) : "l"(v));
    return lo + hi;
}
__device__ __forceinline__ float silu_f(float y) {
    return y * (1.0f / (1.0f + __expf(-y)));
}
__device__ __forceinline__ void red_add_v4(float* p, float4 v) {
    asm volatile("red.global.add.v4.f32 [%0], {%1,%2,%3,%4};"
                 :: "l"(p), "f"(v.x), "f"(v.y), "f"(v.z), "f"(v.w) : "memory");
}

// conflict-free pair layout index: W[k][c] -> base[((kp*4+cc)*32 + lane)*2 + h]
// kp=k>>1, h=k&1, lane=c>>2, cc=c&3 ; per (kp,cc) the LDS.64 has 8B lane stride.
__device__ __forceinline__ int pidx(int k, int c) {
    return (((k >> 1) * 4 + (c & 3)) * 32 + (c >> 2)) * 2 + (k & 1);
}

// ---------------- K fuse: Wf = W_msg2 @ W_upd1[64:192] ----------
__global__ void k_fuse(const float* __restrict__ Wmsg2,
                       const float* __restrict__ Wupd1,
                       const float* __restrict__ bmsg2) {
    int k = blockIdx.x;      // 0..127
    int t = threadIdx.x;     // 0..127
    float acc = 0.f;
#pragma unroll 8
    for (int j = 0; j < HIDDEN; ++j)
        acc = fmaf(Wmsg2[k * HIDDEN + j], Wupd1[(NODE_DIM + j) * HIDDEN + t], acc);
    g_Wf_p[pidx(k, t)] = acc;
    if (k == 0) {
        float c = 0.f;
#pragma unroll 8
        for (int j = 0; j < HIDDEN; ++j)
            c = fmaf(bmsg2[j], Wupd1[(NODE_DIM + j) * HIDDEN + t], c);
        g_c[t] = c;
    }
}

// ---------------- K node_proj: xs = x@W_src, xd = x@W_dst + b1 (FFMA2) ----------
__global__ __launch_bounds__(256)
void k_node_proj(const float* __restrict__ x,
                 const float* __restrict__ Wmsg1,
                 const float* __restrict__ b1, int N) {
    extern __shared__ float sm[];
    float* sWs = sm;             // 8192 (pair layout)
    float* sWd = sWs + 8192;     // 8192
    float* sX  = sWd + 8192;     // 8 warps * 4 nodes * 64 = 2048
    for (int i = threadIdx.x; i < 8192; i += blockDim.x) {
        const int k = i >> 7, c = i & 127;
        const int idx = pidx(k, c);
        sWs[idx] = Wmsg1[i];
        sWd[idx] = Wmsg1[8192 + i];
    }
    __syncthreads();
    const int lane = threadIdx.x & 31, warp = threadIdx.x >> 5;
    const int gw = blockIdx.x * 8 + warp;
    const int nwarps = gridDim.x * 8;
    float* myX = &sX[warp * 4 * 64];
    const float4 b1v = *(const float4*)&b1[lane * 4];

    for (int base = gw * 4; base < N; base += nwarps * 4) {
        __syncwarp();
#pragma unroll
        for (int j = 0; j < 4; ++j) {
            const int n = base + j;
            float2 xv = make_float2(0.f, 0.f);
            if (n < N) xv = *(const float2*)&x[n * NODE_DIM + lane * 2];
            *(float2*)&myX[j * 64 + lane * 2] = xv;
        }
        __syncwarp();
        u64 aS[4][4], aD[4][4];
#pragma unroll
        for (int j = 0; j < 4; ++j)
#pragma unroll
            for (int cc = 0; cc < 4; ++cc) { aS[j][cc] = 0ull; aD[j][cc] = 0ull; }
#pragma unroll
        for (int kp = 0; kp < 32; ++kp) {
            u64 ws[4], wd[4];
#pragma unroll
            for (int cc = 0; cc < 4; ++cc) {
                ws[cc] = *(const u64*)&sWs[((kp * 4 + cc) * 32 + lane) * 2];
                wd[cc] = *(const u64*)&sWd[((kp * 4 + cc) * 32 + lane) * 2];
            }
#pragma unroll
            for (int j = 0; j < 4; ++j) {
                const u64 a = *(const u64*)&myX[j * 64 + kp * 2];
                fma2(aS[j][0], a, ws[0]); fma2(aS[j][1], a, ws[1]);
                fma2(aS[j][2], a, ws[2]); fma2(aS[j][3], a, ws[3]);
                fma2(aD[j][0], a, wd[0]); fma2(aD[j][1], a, wd[1]);
                fma2(aD[j][2], a, wd[2]); fma2(aD[j][3], a, wd[3]);
            }
        }
#pragma unroll
        for (int j = 0; j < 4; ++j) {
            const int n = base + j;
            if (n < N) {
                float4 os = make_float4(psum(aS[j][0]), psum(aS[j][1]),
                                        psum(aS[j][2]), psum(aS[j][3]));
                float4 od = make_float4(psum(aD[j][0]) + b1v.x, psum(aD[j][1]) + b1v.y,
                                        psum(aD[j][2]) + b1v.z, psum(aD[j][3]) + b1v.w);
                *(float4*)&g_xs[(size_t)n * HIDDEN + lane * 4] = os;
                *(float4*)&g_xd[(size_t)n * HIDDEN + lane * 4] = od;
            }
        }
    }
}

// ---------------- K edge: warp per 4 edges, scalar FFMA + shuffle (measured best) ------
__global__ __launch_bounds__(256)
void k_edge(const int* __restrict__ ei, const float* __restrict__ ea,
            const float* __restrict__ Wmsg1,
            const float* __restrict__ gm, const float* __restrict__ bem, int E) {
    __shared__ __align__(16) float sWe[EDGE_DIM * HIDDEN]; // rows 128..159 of W_msg1
    __shared__ __align__(16) float sg[HIDDEN];
    __shared__ __align__(16) float sbe[HIDDEN];
    for (int i = threadIdx.x; i < EDGE_DIM * HIDDEN; i += blockDim.x)
        sWe[i] = Wmsg1[HIDDEN * HIDDEN + i];
    for (int i = threadIdx.x; i < HIDDEN; i += blockDim.x) {
        sg[i] = gm[i]; sbe[i] = bem[i];
    }
    __syncthreads();
    const int lane = threadIdx.x & 31, warp = threadIdx.x >> 5;
    const int gw = blockIdx.x * 8 + warp;
    const int nwarps = gridDim.x * 8;
    const float4 gv  = *(const float4*)&sg[lane * 4];
    const float4 bev = *(const float4*)&sbe[lane * 4];

    for (int base = gw * 4; base < E; base += nwarps * 4) {
        int dsts[4];
        float eav[4];
        float4 acc[4];
#pragma unroll
        for (int j = 0; j < 4; ++j) {
            const int e = base + j;
            if (e < E) {
                const int src = ei[e];
                dsts[j] = ei[E + e];
                const float4 vs = *(const float4*)&g_xs[(size_t)src * HIDDEN + lane * 4];
                const float4 vd = *(const float4*)&g_xd[(size_t)dsts[j] * HIDDEN + lane * 4];
                acc[j].x = vs.x + vd.x;
                acc[j].y = vs.y + vd.y;
                acc[j].z = vs.z + vd.z;
                acc[j].w = vs.w + vd.w;
                eav[j] = ea[(size_t)e * EDGE_DIM + lane];
            } else {
                dsts[j] = -1;
                acc[j] = make_float4(0.f, 0.f, 0.f, 0.f);
                eav[j] = 0.f;
            }
        }
#pragma unroll
        for (int k = 0; k < 32; ++k) {
            const float4 w = *(const float4*)&sWe[k * HIDDEN + lane * 4];
#pragma unroll
            for (int j = 0; j < 4; ++j) {
                const float a = __shfl_sync(0xffffffffu, eav[j], k);
                acc[j].x = fmaf(a, w.x, acc[j].x);
                acc[j].y = fmaf(a, w.y, acc[j].y);
                acc[j].z = fmaf(a, w.z, acc[j].z);
                acc[j].w = fmaf(a, w.w, acc[j].w);
            }
        }
#pragma unroll
        for (int j = 0; j < 4; ++j) {
            if (dsts[j] < 0) continue;
            float s1 = acc[j].x + acc[j].y + acc[j].z + acc[j].w;
            float s2 = fmaf(acc[j].x, acc[j].x, fmaf(acc[j].y, acc[j].y,
                       fmaf(acc[j].z, acc[j].z, acc[j].w * acc[j].w)));
#pragma unroll
            for (int o = 16; o > 0; o >>= 1) {
                s1 += __shfl_xor_sync(0xffffffffu, s1, o);
                s2 += __shfl_xor_sync(0xffffffffu, s2, o);
            }
            const float mu = s1 * (1.0f / HIDDEN);
            const float var = fmaf(-mu, mu, s2 * (1.0f / HIDDEN));
            const float rstd = rsqrtf(var + LN_EPS);
            float4 act;
            act.x = silu_f((acc[j].x - mu) * rstd * gv.x + bev.x);
            act.y = silu_f((acc[j].y - mu) * rstd * gv.y + bev.y);
            act.z = silu_f((acc[j].z - mu) * rstd * gv.z + bev.z);
            act.w = silu_f((acc[j].w - mu) * rstd * gv.w + bev.w);
            red_add_v4(&g_S[(size_t)dsts[j] * HIDDEN + lane * 4], act);
            if (lane == 0) atomicAdd(&g_deg[dsts[j]], 1.0f);
        }
    }
}

// ---------------- K update: fused node update (warp per 4 nodes, FFMA2) ----------------
__global__ __launch_bounds__(256, 1)
void k_update(const float* __restrict__ x,
              const float* __restrict__ Wupd1, const float* __restrict__ bupd1,
              const float* __restrict__ gu, const float* __restrict__ beu,
              const float* __restrict__ Wupd2, const float* __restrict__ bupd2,
              float* __restrict__ out, int N) {
    extern __shared__ float sm[];
    float* sWa = sm;                       // 8192  (pair layout)
    float* sWf = sWa + 8192;               // 16384 (pair layout)
    float* sW2 = sWf + 16384;              // 8192  (interleave, conflict-free)
    float* sb1 = sW2 + 8192;               // 128
    float* sc  = sb1 + HIDDEN;             // 128
    float* sg  = sc  + HIDDEN;             // 128
    float* sbe = sg  + HIDDEN;             // 128
    float* sb2 = sbe + HIDDEN;             // 64
    float* sT  = sb2 + NODE_DIM;           // 8 warps * 4 nodes * 192 = 6144
    for (int i = threadIdx.x; i < 8192; i += blockDim.x) {
        const int k = i >> 7, c = i & 127;
        sWa[pidx(k, c)] = Wupd1[i];
        const int k2 = i >> 6, c2 = i & 63;
        sW2[(k2 >> 1) * 128 + c2 * 2 + (k2 & 1)] = Wupd2[i];
    }
    {
        float4* d = (float4*)sWf; const float4* s = (const float4*)g_Wf_p;
        for (int i = threadIdx.x; i < 4096; i += blockDim.x) d[i] = s[i];
    }
    for (int i = threadIdx.x; i < HIDDEN; i += blockDim.x) {
        sb1[i] = bupd1[i]; sc[i] = g_c[i]; sg[i] = gu[i]; sbe[i] = beu[i];
    }
    for (int i = threadIdx.x; i < NODE_DIM; i += blockDim.x) sb2[i] = bupd2[i];
    __syncthreads();

    const int lane = threadIdx.x & 31, warp = threadIdx.x >> 5;
    const int gw = blockIdx.x * 8 + warp;
    const int nwarps = gridDim.x * 8;
    float* myT = &sT[warp * 4 * 192];   // per node: [0..63]=x, [64..191]=S then act

    const float4 b1v = *(const float4*)&sb1[lane * 4];
    const float4 cv  = *(const float4*)&sc [lane * 4];
    const float4 gv  = *(const float4*)&sg [lane * 4];
    const float4 bev = *(const float4*)&sbe[lane * 4];
    const float2 b2v = *(const float2*)&sb2[lane * 2];

    for (int base = gw * 4; base < N; base += nwarps * 4) {
        __syncwarp();
        u64 acc[4][4];
#pragma unroll
        for (int j = 0; j < 4; ++j) {
            const int n = base + j;
            float2 xv = make_float2(0.f, 0.f);
            float4 s4 = make_float4(0.f, 0.f, 0.f, 0.f);
            float dg = 0.f;
            if (n < N) {
                xv = *(const float2*)&x[n * NODE_DIM + lane * 2];
                s4 = *(const float4*)&g_S[(size_t)n * HIDDEN + lane * 4];
                dg = g_deg[n];
            }
            *(float2*)&myT[j * 192 + lane * 2] = xv;
            *(float4*)&myT[j * 192 + 64 + lane * 4] = s4;
            acc[j][0] = pk(fmaf(dg, cv.x, b1v.x), 0.f);
            acc[j][1] = pk(fmaf(dg, cv.y, b1v.y), 0.f);
            acc[j][2] = pk(fmaf(dg, cv.z, b1v.z), 0.f);
            acc[j][3] = pk(fmaf(dg, cv.w, b1v.w), 0.f);
        }
        __syncwarp();
        // loop1: x @ W_upd1[0:64]
#pragma unroll
        for (int kp = 0; kp < 32; ++kp) {
            u64 w[4];
#pragma unroll
            for (int cc = 0; cc < 4; ++cc)
                w[cc] = *(const u64*)&sWa[((kp * 4 + cc) * 32 + lane) * 2];
#pragma unroll
            for (int j = 0; j < 4; ++j) {
                const u64 a = *(const u64*)&myT[j * 192 + kp * 2];
                fma2(acc[j][0], a, w[0]); fma2(acc[j][1], a, w[1]);
                fma2(acc[j][2], a, w[2]); fma2(acc[j][3], a, w[3]);
            }
        }
        // loop2: S @ Wf
#pragma unroll
        for (int kp = 0; kp < 64; ++kp) {
            u64 w[4];
#pragma unroll
            for (int cc = 0; cc < 4; ++cc)
                w[cc] = *(const u64*)&sWf[((kp * 4 + cc) * 32 + lane) * 2];
#pragma unroll
            for (int j = 0; j < 4; ++j) {
                const u64 a = *(const u64*)&myT[j * 192 + 64 + kp * 2];
                fma2(acc[j][0], a, w[0]); fma2(acc[j][1], a, w[1]);
                fma2(acc[j][2], a, w[2]); fma2(acc[j][3], a, w[3]);
            }
        }
        __syncwarp();
        // LayerNorm (one pass) + SiLU, store act into the S slots
#pragma unroll
        for (int j = 0; j < 4; ++j) {
            const float v0 = psum(acc[j][0]), v1 = psum(acc[j][1]);
            const float v2 = psum(acc[j][2]), v3 = psum(acc[j][3]);
            float s1 = v0 + v1 + v2 + v3;
            float s2 = fmaf(v0, v0, fmaf(v1, v1, fmaf(v2, v2, v3 * v3)));
#pragma unroll
            for (int o = 16; o > 0; o >>= 1) {
                s1 += __shfl_xor_sync(0xffffffffu, s1, o);
                s2 += __shfl_xor_sync(0xffffffffu, s2, o);
            }
            const float mu = s1 * (1.0f / HIDDEN);
            const float var = fmaf(-mu, mu, s2 * (1.0f / HIDDEN));
            const float rstd = rsqrtf(var + LN_EPS);
            float4 act;
            act.x = silu_f((v0 - mu) * rstd * gv.x + bev.x);
            act.y = silu_f((v1 - mu) * rstd * gv.y + bev.y);
            act.z = silu_f((v2 - mu) * rstd * gv.z + bev.z);
            act.w = silu_f((v3 - mu) * rstd * gv.w + bev.w);
            *(float4*)&myT[j * 192 + 64 + lane * 4] = act;
        }
        __syncwarp();
        // loop3: act @ W_upd2 (128 -> 64)
        u64 o0[4], o1[4];
#pragma unroll
        for (int j = 0; j < 4; ++j) { o0[j] = 0ull; o1[j] = 0ull; }
#pragma unroll
        for (int kp = 0; kp < 64; ++kp) {
            const ulonglong2 w = *(const ulonglong2*)&sW2[kp * 128 + lane * 4];
#pragma unroll
            for (int j = 0; j < 4; ++j) {
                const u64 a = *(const u64*)&myT[j * 192 + 64 + kp * 2];
                fma2(o0[j], a, w.x); fma2(o1[j], a, w.y);
            }
        }
#pragma unroll
        for (int j = 0; j < 4; ++j) {
            const int n = base + j;
            if (n < N) {
                const float2 xv = *(const float2*)&myT[j * 192 + lane * 2];
                float2 res;
                res.x = xv.x + psum(o0[j]) + b2v.x;
                res.y = xv.y + psum(o1[j]) + b2v.y;
                *(float2*)&out[(size_t)n * NODE_DIM + lane * 2] = res;
            }
        }
    }
}

// ---------------- host ----------------
extern "C" void kernel_launch(void* const* d_in, const int* in_sizes, int n_in,
                              void* d_out, int out_size) {
    const float* x      = (const float*)d_in[0];
    const int*   ei     = (const int*)  d_in[1];
    const float* ea     = (const float*)d_in[2];
    const float* Wmsg1  = (const float*)d_in[3];
    const float* bmsg1  = (const float*)d_in[4];
    const float* gmsg   = (const float*)d_in[5];
    const float* bemsg  = (const float*)d_in[6];
    const float* Wmsg2  = (const float*)d_in[7];
    const float* bmsg2  = (const float*)d_in[8];
    const float* Wupd1  = (const float*)d_in[9];
    const float* bupd1  = (const float*)d_in[10];
    const float* gupd   = (const float*)d_in[11];
    const float* beupd  = (const float*)d_in[12];
    const float* Wupd2  = (const float*)d_in[13];
    const float* bupd2  = (const float*)d_in[14];
    float* out = (float*)d_out;

    const int N = in_sizes[0] / NODE_DIM;
    const int E = in_sizes[2] / EDGE_DIM;

    void *pS = nullptr, *pdeg = nullptr;
    cudaGetSymbolAddress(&pS, g_S);
    cudaGetSymbolAddress(&pdeg, g_deg);
    cudaMemsetAsync(pS, 0, (size_t)N * HIDDEN * sizeof(float), 0);
    cudaMemsetAsync(pdeg, 0, (size_t)N * sizeof(float), 0);

    const int smem_proj = (8192 + 8192 + 2048) * sizeof(float);                    // 72 KB
    const int smem_upd  = (8192 + 16384 + 8192 + 4 * HIDDEN + NODE_DIM + 6144) * sizeof(float); // ~158 KB
    cudaFuncSetAttribute(k_node_proj, cudaFuncAttributeMaxDynamicSharedMemorySize, smem_proj);
    cudaFuncSetAttribute(k_update,    cudaFuncAttributeMaxDynamicSharedMemorySize, smem_upd);

    // launch order: 4th non-memset kernel = k_update (ncu capture target this round)
    k_fuse<<<HIDDEN, HIDDEN>>>(Wmsg2, Wupd1, bmsg2);
    k_node_proj<<<296, 256, smem_proj>>>(x, Wmsg1, bmsg1, N);
    k_edge<<<1184, 256>>>(ei, ea, Wmsg1, gmsg, bemsg, E);
    k_update<<<148, 256, smem_upd>>>(x, Wupd1, bupd1, gupd, beupd, Wupd2, bupd2, out, N);
}